// round 1
// baseline (speedup 1.0000x reference)
#include <cuda_runtime.h>
#include <cuda_bf16.h>

// Problem constants (fixed by the dataset)
#define NN 100000
#define EE 3200000

// Scratch (device globals; no allocation allowed)
__device__ float g_dinv[NN];        // degree -> dinv (in place)
__device__ float g_norm[EE];        // per-edge symmetric norm
__device__ float g_agg[NN * 64];    // aggregation buffer (max width 64); reused as t[N,2] at the end
__device__ float g_h[NN * 64];      // hidden activations h1/h2/h3 (reused)
__device__ float g_wf[2 * 64];      // fused Wl@W4
__device__ float g_bf[2];           // fused Wl@b4 + bl

// ---------------- vector reductions (no-return atomics) ----------------
__device__ __forceinline__ void red_add_v4(float4* addr, float4 v) {
    asm volatile("red.global.add.v4.f32 [%0], {%1,%2,%3,%4};"
                 :: "l"(addr), "f"(v.x), "f"(v.y), "f"(v.z), "f"(v.w) : "memory");
}
__device__ __forceinline__ void red_add_v2(float2* addr, float2 v) {
    asm volatile("red.global.add.v2.f32 [%0], {%1,%2};"
                 :: "l"(addr), "f"(v.x), "f"(v.y) : "memory");
}

// ---------------- degree / norm precompute ----------------
__global__ void k_fill_deg(int n) {
    int v = blockIdx.x * blockDim.x + threadIdx.x;
    if (v < n) g_dinv[v] = 1.0f;  // self-loop contributes 1 to degree
}
__global__ void k_deg_edges(const int* __restrict__ dst, int E) {
    int e = blockIdx.x * blockDim.x + threadIdx.x;
    if (e < E) atomicAdd(&g_dinv[dst[e]], 1.0f);
}
__global__ void k_dinv(int n) {
    int v = blockIdx.x * blockDim.x + threadIdx.x;
    if (v < n) {
        float d = g_dinv[v];
        g_dinv[v] = (d > 0.0f) ? rsqrtf(d) : 0.0f;
    }
}
__global__ void k_norm(const int* __restrict__ src, const int* __restrict__ dst, int E) {
    int e = blockIdx.x * blockDim.x + threadIdx.x;
    if (e < E) g_norm[e] = g_dinv[src[e]] * g_dinv[dst[e]];
}

// ---------------- fuse W4/b4 with Wl/bl: Wf = Wl@W4 [2,64], bf = Wl@b4 + bl ----------------
__global__ void k_fuse(const float* __restrict__ W4, const float* __restrict__ b4,
                       const float* __restrict__ Wl, const float* __restrict__ bl) {
    int k = threadIdx.x;   // 0..63
    int j = blockIdx.x;    // 0..1
    float a = 0.0f;
#pragma unroll
    for (int m = 0; m < 10; m++) a += Wl[j * 10 + m] * W4[m * 64 + k];
    g_wf[j * 64 + k] = a;
    if (k == 0) {
        float bb = bl[j];
#pragma unroll
        for (int m = 0; m < 10; m++) bb += Wl[j * 10 + m] * b4[m];
        g_bf[j] = bb;
    }
}

// ---------------- init agg with self-loop term: agg[v] = dinv[v]^2 * xin[v] ----------------
// C = number of float4 chunks per row (row width / 4)
template <int C>
__global__ void k_init_self(const float* __restrict__ xin, float* __restrict__ agg, int n) {
    int i = blockIdx.x * blockDim.x + threadIdx.x;
    if (i >= n * C) return;
    int v = i / C;
    float d = g_dinv[v];
    float d2 = d * d;
    float4 val = reinterpret_cast<const float4*>(xin)[i];
    float4 r = make_float4(val.x * d2, val.y * d2, val.z * d2, val.w * d2);
    reinterpret_cast<float4*>(agg)[i] = r;
}

// ---------------- edge scatter: agg[dst] += norm * xin[src], float4 chunks ----------------
template <int C>
__global__ void __launch_bounds__(256) k_scatter(const float* __restrict__ xin,
                                                 float* __restrict__ agg,
                                                 const int* __restrict__ src,
                                                 const int* __restrict__ dst, int E) {
    int i = blockIdx.x * blockDim.x + threadIdx.x;
    if (i >= E * C) return;
    int e = i / C;
    int c = i - e * C;
    int s = src[e];
    int d = dst[e];
    float nm = g_norm[e];
    float4 v = reinterpret_cast<const float4*>(xin)[s * C + c];
    float4 r = make_float4(v.x * nm, v.y * nm, v.z * nm, v.w * nm);
    red_add_v4(reinterpret_cast<float4*>(agg) + (d * C + c), r);
}

// ---------------- dense transform: out = [relu](agg @ W^T + b) ----------------
template <int IN, int OUT, bool RELU>
__global__ void k_transform(const float* __restrict__ agg, const float* __restrict__ W,
                            const float* __restrict__ b, float* __restrict__ out, int n) {
    __shared__ float sW[OUT * IN];
    __shared__ float sb[OUT];
    for (int k = threadIdx.x; k < OUT * IN; k += blockDim.x) sW[k] = W[k];
    if (threadIdx.x < OUT) sb[threadIdx.x] = b[threadIdx.x];
    __syncthreads();
    int t = blockIdx.x * blockDim.x + threadIdx.x;
    int v = t / OUT;
    int j = t - v * OUT;
    if (v >= n) return;
    const float* row = agg + v * IN;
    float acc = sb[j];
#pragma unroll
    for (int k = 0; k < IN; k++) acc = fmaf(row[k], sW[j * IN + k], acc);
    out[v * OUT + j] = RELU ? fmaxf(acc, 0.0f) : acc;
}

// ---------------- fused head: t[v] = h3[v] @ Wf^T  (one warp per node, coalesced) ----------------
__global__ void k_t45(const float* __restrict__ h, float* __restrict__ t, int n) {
    int gtid = blockIdx.x * blockDim.x + threadIdx.x;
    int warp = gtid >> 5;
    int lane = threadIdx.x & 31;
    if (warp >= n) return;
    float2 r = reinterpret_cast<const float2*>(h + warp * 64)[lane];
    float a0 = r.x * g_wf[2 * lane]      + r.y * g_wf[2 * lane + 1];
    float a1 = r.x * g_wf[64 + 2 * lane] + r.y * g_wf[64 + 2 * lane + 1];
#pragma unroll
    for (int o = 16; o > 0; o >>= 1) {
        a0 += __shfl_down_sync(0xffffffffu, a0, o);
        a1 += __shfl_down_sync(0xffffffffu, a1, o);
    }
    if (lane == 0) {
        t[warp * 2 + 0] = a0;
        t[warp * 2 + 1] = a1;
    }
}

// ---------------- final output: init with bias + self-loop, then width-2 edge scatter ----------------
__global__ void k_out_init(const float* __restrict__ t, float* __restrict__ out, int n) {
    int v = blockIdx.x * blockDim.x + threadIdx.x;
    if (v >= n) return;
    float d = g_dinv[v];
    float d2 = d * d;
    float2 tv = reinterpret_cast<const float2*>(t)[v];
    float2 o;
    o.x = g_bf[0] + d2 * tv.x;
    o.y = g_bf[1] + d2 * tv.y;
    reinterpret_cast<float2*>(out)[v] = o;
}
__global__ void k_out_scatter(const float* __restrict__ t, float* __restrict__ out,
                              const int* __restrict__ src, const int* __restrict__ dst, int E) {
    int e = blockIdx.x * blockDim.x + threadIdx.x;
    if (e >= E) return;
    float nm = g_norm[e];
    float2 tv = reinterpret_cast<const float2*>(t)[src[e]];
    red_add_v2(reinterpret_cast<float2*>(out) + dst[e], make_float2(tv.x * nm, tv.y * nm));
}

extern "C" void kernel_launch(void* const* d_in, const int* in_sizes, int n_in,
                              void* d_out, int out_size) {
    const float* x  = (const float*)d_in[0];
    const int*   ei = (const int*)d_in[1];
    const float* W1 = (const float*)d_in[2];
    const float* b1 = (const float*)d_in[3];
    const float* W2 = (const float*)d_in[4];
    const float* b2 = (const float*)d_in[5];
    const float* W3 = (const float*)d_in[6];
    const float* b3 = (const float*)d_in[7];
    const float* W4 = (const float*)d_in[8];
    const float* b4 = (const float*)d_in[9];
    const float* Wl = (const float*)d_in[10];
    const float* bl = (const float*)d_in[11];
    float* out = (float*)d_out;

    int n = in_sizes[0] / 8;   // 100000
    int E = in_sizes[1] / 2;   // 3200000
    const int* src = ei;       // edge_index[0]
    const int* dst = ei + E;   // edge_index[1]

    float *agg, *h;
    cudaGetSymbolAddress((void**)&agg, g_agg);
    cudaGetSymbolAddress((void**)&h, g_h);

    const int B = 256;
    auto blocks = [&](long total) { return (int)((total + B - 1) / B); };

    // degree / dinv / norm
    k_fill_deg<<<blocks(n), B>>>(n);
    k_deg_edges<<<blocks(E), B>>>(dst, E);
    k_dinv<<<blocks(n), B>>>(n);
    k_norm<<<blocks(E), B>>>(src, dst, E);
    k_fuse<<<2, 64>>>(W4, b4, Wl, bl);

    // Layer 1: aggregate x at width 8 (C=2), then 8->16 + relu
    k_init_self<2><<<blocks((long)n * 2), B>>>(x, agg, n);
    k_scatter<2><<<blocks((long)E * 2), B>>>(x, agg, src, dst, E);
    k_transform<8, 16, true><<<blocks((long)n * 16), B>>>(agg, W1, b1, h, n);

    // Layer 2: aggregate h1 at width 16 (C=4), then 16->64 + relu
    k_init_self<4><<<blocks((long)n * 4), B>>>(h, agg, n);
    k_scatter<4><<<blocks((long)E * 4), B>>>(h, agg, src, dst, E);
    k_transform<16, 64, true><<<blocks((long)n * 64), B>>>(agg, W2, b2, h, n);

    // Layer 3: aggregate h2 at width 64 (C=16), then 64->64 + relu
    k_init_self<16><<<blocks((long)n * 16), B>>>(h, agg, n);
    k_scatter<16><<<blocks((long)E * 16), B>>>(h, agg, src, dst, E);
    k_transform<64, 64, true><<<blocks((long)n * 64), B>>>(agg, W3, b3, h, n);

    // Fused layers 4+5: t = h3 @ (Wl@W4)^T [N,2]; out = Agg(t) + bf
    k_t45<<<blocks((long)n * 32), B>>>(h, agg, n);            // t lives in g_agg
    k_out_init<<<blocks(n), B>>>(agg, out, n);
    k_out_scatter<<<blocks(E), B>>>(agg, out, src, dst, E);
}

// round 3
// speedup vs baseline: 1.1424x; 1.1424x over previous
#include <cuda_runtime.h>
#include <cuda_bf16.h>

// Problem constants (fixed by the dataset)
#define NN 100000
#define EE 3200000
#define SCAN_TILE 1024

// Scratch (device globals; no allocation allowed)
__device__ float g_dinv[NN];          // 1/sqrt(deg)
__device__ int   g_count[NN];         // per-dst in-degree (excl self loop)
__device__ int   g_rowstart[NN];      // CSR row offsets (exclusive scan of count)
__device__ int   g_cursor[NN];        // placement cursors
__device__ int   g_bsum[128];         // scan block sums
__device__ int2  g_perm[EE];          // packed (src, norm bits), dst-sorted
__device__ float g_agg[NN * 64];      // aggregation buffer (also t[N,2] at the end)
__device__ float g_h[NN * 64];        // hidden activations
__device__ float g_wf[2 * 64];        // fused Wl@W4
__device__ float g_bf[2];             // fused Wl@b4 + bl

// ---------------- CSR build ----------------
__global__ void k_zero(int n) {
    int v = blockIdx.x * blockDim.x + threadIdx.x;
    if (v < n) { g_count[v] = 0; g_cursor[v] = 0; }
}
__global__ void k_count(const int* __restrict__ dst, int E) {
    int e = blockIdx.x * blockDim.x + threadIdx.x;
    if (e < E) atomicAdd(&g_count[dst[e]], 1);
}
__global__ void k_dinv(int n) {
    int v = blockIdx.x * blockDim.x + threadIdx.x;
    if (v < n) g_dinv[v] = rsqrtf((float)(g_count[v] + 1));   // +1: self loop
}
// scan step 1: per-1024-tile sums
__global__ void k_scan1(int n) {
    __shared__ int s[256];
    int base = blockIdx.x * SCAN_TILE;
    int t = threadIdx.x;
    int sum = 0;
    for (int i = t; i < SCAN_TILE; i += 256) {
        int idx = base + i;
        if (idx < n) sum += g_count[idx];
    }
    s[t] = sum; __syncthreads();
    for (int o = 128; o > 0; o >>= 1) { if (t < o) s[t] += s[t + o]; __syncthreads(); }
    if (t == 0) g_bsum[blockIdx.x] = s[0];
}
// scan step 2: exclusive scan of tile sums (single block)
__global__ void k_scan2(int nb) {
    __shared__ int s[128];
    int t = threadIdx.x;
    int orig = (t < nb) ? g_bsum[t] : 0;
    s[t] = orig; __syncthreads();
    for (int o = 1; o < 128; o <<= 1) {
        int v = (t >= o) ? s[t - o] : 0;
        __syncthreads();
        s[t] += v;
        __syncthreads();
    }
    if (t < nb) g_bsum[t] = s[t] - orig;
}
// scan step 3: per-tile exclusive scan + offset -> rowstart
__global__ void k_scan3(int n) {
    __shared__ int s[256];
    int base = blockIdx.x * SCAN_TILE;
    int t = threadIdx.x;
    int c[4]; int tot = 0;
#pragma unroll
    for (int k = 0; k < 4; k++) {
        int idx = base + t * 4 + k;
        c[k] = (idx < n) ? g_count[idx] : 0;
        tot += c[k];
    }
    s[t] = tot; __syncthreads();
    for (int o = 1; o < 256; o <<= 1) {
        int v = (t >= o) ? s[t - o] : 0;
        __syncthreads();
        s[t] += v;
        __syncthreads();
    }
    int off = g_bsum[blockIdx.x] + s[t] - tot;
#pragma unroll
    for (int k = 0; k < 4; k++) {
        int idx = base + t * 4 + k;
        if (idx < n) { g_rowstart[idx] = off; off += c[k]; }
    }
}
// place edges into dst-sorted order, packing (src, norm)
__global__ void k_build(const int* __restrict__ src, const int* __restrict__ dst, int E) {
    int e = blockIdx.x * blockDim.x + threadIdx.x;
    if (e >= E) return;
    int s = src[e], d = dst[e];
    float nm = g_dinv[s] * g_dinv[d];
    int pos = g_rowstart[d] + atomicAdd(&g_cursor[d], 1);
    g_perm[pos] = make_int2(s, __float_as_int(nm));
}

// ---------------- fuse W4/b4 with Wl/bl ----------------
__global__ void k_fuse(const float* __restrict__ W4, const float* __restrict__ b4,
                       const float* __restrict__ Wl, const float* __restrict__ bl) {
    int k = threadIdx.x;   // 0..63
    int j = blockIdx.x;    // 0..1
    float a = 0.0f;
#pragma unroll
    for (int m = 0; m < 10; m++) a += Wl[j * 10 + m] * W4[m * 64 + k];
    g_wf[j * 64 + k] = a;
    if (k == 0) {
        float bb = bl[j];
#pragma unroll
        for (int m = 0; m < 10; m++) bb += Wl[j * 10 + m] * b4[m];
        g_bf[j] = bb;
    }
}

// ---------------- gather aggregation kernels ----------------
// width 8: 8 lanes per node, 1 float/lane
__global__ void __launch_bounds__(256) k_gather8(const float* __restrict__ xin,
                                                 float* __restrict__ agg, int n) {
    int t = blockIdx.x * blockDim.x + threadIdx.x;
    int v = t >> 3, sub = t & 7;
    if (v >= n) return;
    int base = g_rowstart[v], cnt = g_count[v];
    float dv = g_dinv[v];
    float acc = __ldg(&xin[v * 8 + sub]) * dv * dv;
    int i = 0;
    for (; i + 4 <= cnt; i += 4) {
        int2 p0 = __ldg(&g_perm[base + i + 0]);
        int2 p1 = __ldg(&g_perm[base + i + 1]);
        int2 p2 = __ldg(&g_perm[base + i + 2]);
        int2 p3 = __ldg(&g_perm[base + i + 3]);
        float v0 = __ldg(&xin[p0.x * 8 + sub]), v1 = __ldg(&xin[p1.x * 8 + sub]);
        float v2 = __ldg(&xin[p2.x * 8 + sub]), v3 = __ldg(&xin[p3.x * 8 + sub]);
        acc = fmaf(__int_as_float(p0.y), v0, acc);
        acc = fmaf(__int_as_float(p1.y), v1, acc);
        acc = fmaf(__int_as_float(p2.y), v2, acc);
        acc = fmaf(__int_as_float(p3.y), v3, acc);
    }
    for (; i < cnt; i++) {
        int2 p = __ldg(&g_perm[base + i]);
        acc = fmaf(__int_as_float(p.y), __ldg(&xin[p.x * 8 + sub]), acc);
    }
    agg[v * 8 + sub] = acc;
}
// width 16: 16 lanes per node, 1 float/lane
__global__ void __launch_bounds__(256) k_gather16(const float* __restrict__ xin,
                                                  float* __restrict__ agg, int n) {
    int t = blockIdx.x * blockDim.x + threadIdx.x;
    int v = t >> 4, sub = t & 15;
    if (v >= n) return;
    int base = g_rowstart[v], cnt = g_count[v];
    float dv = g_dinv[v];
    float acc = __ldg(&xin[v * 16 + sub]) * dv * dv;
    int i = 0;
    for (; i + 4 <= cnt; i += 4) {
        int2 p0 = __ldg(&g_perm[base + i + 0]);
        int2 p1 = __ldg(&g_perm[base + i + 1]);
        int2 p2 = __ldg(&g_perm[base + i + 2]);
        int2 p3 = __ldg(&g_perm[base + i + 3]);
        float v0 = __ldg(&xin[p0.x * 16 + sub]), v1 = __ldg(&xin[p1.x * 16 + sub]);
        float v2 = __ldg(&xin[p2.x * 16 + sub]), v3 = __ldg(&xin[p3.x * 16 + sub]);
        acc = fmaf(__int_as_float(p0.y), v0, acc);
        acc = fmaf(__int_as_float(p1.y), v1, acc);
        acc = fmaf(__int_as_float(p2.y), v2, acc);
        acc = fmaf(__int_as_float(p3.y), v3, acc);
    }
    for (; i < cnt; i++) {
        int2 p = __ldg(&g_perm[base + i]);
        acc = fmaf(__int_as_float(p.y), __ldg(&xin[p.x * 16 + sub]), acc);
    }
    agg[v * 16 + sub] = acc;
}
// width 64: one warp per node, float2/lane (row read = 256B fully coalesced), unroll 8
__global__ void __launch_bounds__(256) k_gather64(const float* __restrict__ xin,
                                                  float* __restrict__ agg, int n) {
    int w = (blockIdx.x * blockDim.x + threadIdx.x) >> 5;
    int lane = threadIdx.x & 31;
    if (w >= n) return;
    int base = g_rowstart[w], cnt = g_count[w];
    float dv = g_dinv[w];
    const float2* xv = reinterpret_cast<const float2*>(xin);
    float2 acc = __ldg(&xv[w * 32 + lane]);
    acc.x *= dv * dv; acc.y *= dv * dv;
    int i = 0;
    for (; i + 8 <= cnt; i += 8) {
        int2 p[8];
        float2 vv[8];
#pragma unroll
        for (int k = 0; k < 8; k++) p[k] = __ldg(&g_perm[base + i + k]);
#pragma unroll
        for (int k = 0; k < 8; k++) vv[k] = __ldg(&xv[p[k].x * 32 + lane]);
#pragma unroll
        for (int k = 0; k < 8; k++) {
            float nm = __int_as_float(p[k].y);
            acc.x = fmaf(nm, vv[k].x, acc.x);
            acc.y = fmaf(nm, vv[k].y, acc.y);
        }
    }
    for (; i < cnt; i++) {
        int2 p = __ldg(&g_perm[base + i]);
        float2 v0 = __ldg(&xv[p.x * 32 + lane]);
        float nm = __int_as_float(p.y);
        acc.x = fmaf(nm, v0.x, acc.x); acc.y = fmaf(nm, v0.y, acc.y);
    }
    reinterpret_cast<float2*>(agg)[w * 32 + lane] = acc;
}

// ---------------- dense transform: out = [relu](agg @ W^T + b) ----------------
template <int IN, int OUT, bool RELU>
__global__ void k_transform(const float* __restrict__ agg, const float* __restrict__ W,
                            const float* __restrict__ b, float* __restrict__ out, int n) {
    __shared__ float sW[OUT * IN];
    __shared__ float sb[OUT];
    for (int k = threadIdx.x; k < OUT * IN; k += blockDim.x) sW[k] = W[k];
    if (threadIdx.x < OUT) sb[threadIdx.x] = b[threadIdx.x];
    __syncthreads();
    int t = blockIdx.x * blockDim.x + threadIdx.x;
    int v = t / OUT;
    int j = t - v * OUT;
    if (v >= n) return;
    const float* row = agg + v * IN;
    float acc = sb[j];
#pragma unroll
    for (int k = 0; k < IN; k++) acc = fmaf(row[k], sW[j * IN + k], acc);
    out[v * OUT + j] = RELU ? fmaxf(acc, 0.0f) : acc;
}

// ---------------- fused head: t[v] = h3[v] @ Wf^T (one warp per node) ----------------
__global__ void k_t45(const float* __restrict__ h, float* __restrict__ t, int n) {
    int gtid = blockIdx.x * blockDim.x + threadIdx.x;
    int warp = gtid >> 5;
    int lane = threadIdx.x & 31;
    if (warp >= n) return;
    float2 r = reinterpret_cast<const float2*>(h + warp * 64)[lane];
    float a0 = r.x * g_wf[2 * lane]      + r.y * g_wf[2 * lane + 1];
    float a1 = r.x * g_wf[64 + 2 * lane] + r.y * g_wf[64 + 2 * lane + 1];
#pragma unroll
    for (int o = 16; o > 0; o >>= 1) {
        a0 += __shfl_down_sync(0xffffffffu, a0, o);
        a1 += __shfl_down_sync(0xffffffffu, a1, o);
    }
    if (lane == 0) {
        t[warp * 2 + 0] = a0;
        t[warp * 2 + 1] = a1;
    }
}

// ---------------- final: out[v] = bf + dinv^2*t[v] + sum nm*t[src], thread per node ----------------
__global__ void __launch_bounds__(256) k_out(const float* __restrict__ t2,
                                             float* __restrict__ out, int n) {
    int v = blockIdx.x * blockDim.x + threadIdx.x;
    if (v >= n) return;
    int base = g_rowstart[v], cnt = g_count[v];
    float dv = g_dinv[v];
    const float2* tv = reinterpret_cast<const float2*>(t2);
    float2 self = __ldg(&tv[v]);
    float2 acc;
    acc.x = g_bf[0] + dv * dv * self.x;
    acc.y = g_bf[1] + dv * dv * self.y;
    int i = 0;
    for (; i + 8 <= cnt; i += 8) {
        int2 p[8];
        float2 vv[8];
#pragma unroll
        for (int k = 0; k < 8; k++) p[k] = __ldg(&g_perm[base + i + k]);
#pragma unroll
        for (int k = 0; k < 8; k++) vv[k] = __ldg(&tv[p[k].x]);
#pragma unroll
        for (int k = 0; k < 8; k++) {
            float nm = __int_as_float(p[k].y);
            acc.x = fmaf(nm, vv[k].x, acc.x);
            acc.y = fmaf(nm, vv[k].y, acc.y);
        }
    }
    for (; i < cnt; i++) {
        int2 p = __ldg(&g_perm[base + i]);
        float2 s = __ldg(&tv[p.x]);
        float nm = __int_as_float(p.y);
        acc.x = fmaf(nm, s.x, acc.x); acc.y = fmaf(nm, s.y, acc.y);
    }
    reinterpret_cast<float2*>(out)[v] = acc;
}

extern "C" void kernel_launch(void* const* d_in, const int* in_sizes, int n_in,
                              void* d_out, int out_size) {
    const float* x  = (const float*)d_in[0];
    const int*   ei = (const int*)d_in[1];
    const float* W1 = (const float*)d_in[2];
    const float* b1 = (const float*)d_in[3];
    const float* W2 = (const float*)d_in[4];
    const float* b2 = (const float*)d_in[5];
    const float* W3 = (const float*)d_in[6];
    const float* b3 = (const float*)d_in[7];
    const float* W4 = (const float*)d_in[8];
    const float* b4 = (const float*)d_in[9];
    const float* Wl = (const float*)d_in[10];
    const float* bl = (const float*)d_in[11];
    float* out = (float*)d_out;

    int n = in_sizes[0] / 8;   // 100000
    int E = in_sizes[1] / 2;   // 3200000
    const int* src = ei;       // edge_index[0]
    const int* dst = ei + E;   // edge_index[1]

    float *agg, *h;
    cudaGetSymbolAddress((void**)&agg, g_agg);
    cudaGetSymbolAddress((void**)&h, g_h);

    const int B = 256;
    auto blocks = [&](long total) { return (int)((total + B - 1) / B); };
    int nscan = (n + SCAN_TILE - 1) / SCAN_TILE;

    // CSR build: counts -> dinv -> scan -> placement
    k_zero<<<blocks(n), B>>>(n);
    k_count<<<blocks(E), B>>>(dst, E);
    k_dinv<<<blocks(n), B>>>(n);
    k_scan1<<<nscan, 256>>>(n);
    k_scan2<<<1, 128>>>(nscan);
    k_scan3<<<nscan, 256>>>(n);
    k_build<<<blocks(E), B>>>(src, dst, E);
    k_fuse<<<2, 64>>>(W4, b4, Wl, bl);

    // Layer 1: gather x (w=8), transform 8->16 + relu
    k_gather8<<<blocks((long)n * 8), B>>>(x, agg, n);
    k_transform<8, 16, true><<<blocks((long)n * 16), B>>>(agg, W1, b1, h, n);

    // Layer 2: gather h1 (w=16), transform 16->64 + relu
    k_gather16<<<blocks((long)n * 16), B>>>(h, agg, n);
    k_transform<16, 64, true><<<blocks((long)n * 64), B>>>(agg, W2, b2, h, n);

    // Layer 3: gather h2 (w=64, warp/node), transform 64->64 + relu
    k_gather64<<<blocks((long)n * 32), B>>>(h, agg, n);
    k_transform<64, 64, true><<<blocks((long)n * 64), B>>>(agg, W3, b3, h, n);

    // Fused layers 4+5: t = h3 @ (Wl@W4)^T [N,2]; out = Agg(t) + bf
    k_t45<<<blocks((long)n * 32), B>>>(h, agg, n);   // t lives in g_agg
    k_out<<<blocks(n), B>>>(agg, out, n);
}

// round 6
// speedup vs baseline: 1.6859x; 1.4758x over previous
#include <cuda_runtime.h>
#include <cuda_fp16.h>

// Problem constants (fixed by the dataset)
#define NN 100000
#define EE 3200000
#define SCAN_TILE 1024

// Scratch (device globals; no allocation allowed). Kernels reference these
// directly — kernel_launch makes no runtime-API calls besides launches.
__device__ float g_dinv[NN];              // 1/sqrt(deg)
__device__ int   g_count[NN];             // per-dst in-degree (excl self loop)
__device__ int   g_rowstart[NN];          // CSR row offsets
__device__ int   g_cursor[NN];            // placement cursors
__device__ int   g_bsum[128];             // scan block sums
__device__ int2  g_perm[EE];              // packed (src, norm bits), dst-sorted
__device__ __align__(16) float g_h1[NN * 16];   // h1 fp32
__device__ __align__(16) __half2 g_h2[NN * 32]; // h2 fp16 (64 halves/node)
__device__ __align__(16) float2 g_t[NN];        // t[N,2]
__device__ float g_wf[2 * 64];            // fused Wl@W4
__device__ float g_bf[2];                 // fused Wl@b4 + bl

// ---------------- CSR build ----------------
__global__ void k_zero(int n) {
    int v = blockIdx.x * blockDim.x + threadIdx.x;
    if (v < n) { g_count[v] = 0; g_cursor[v] = 0; }
}
__global__ void k_count(const int* __restrict__ dst, int E) {
    int e = blockIdx.x * blockDim.x + threadIdx.x;
    if (e < E) atomicAdd(&g_count[dst[e]], 1);
}
__global__ void k_dinv(int n) {
    int v = blockIdx.x * blockDim.x + threadIdx.x;
    if (v < n) g_dinv[v] = rsqrtf((float)(g_count[v] + 1));   // +1: self loop
}
__global__ void k_scan1(int n) {
    __shared__ int s[256];
    int base = blockIdx.x * SCAN_TILE;
    int t = threadIdx.x;
    int sum = 0;
    for (int i = t; i < SCAN_TILE; i += 256) {
        int idx = base + i;
        if (idx < n) sum += g_count[idx];
    }
    s[t] = sum; __syncthreads();
    for (int o = 128; o > 0; o >>= 1) { if (t < o) s[t] += s[t + o]; __syncthreads(); }
    if (t == 0) g_bsum[blockIdx.x] = s[0];
}
__global__ void k_scan2(int nb) {
    __shared__ int s[128];
    int t = threadIdx.x;
    int orig = (t < nb) ? g_bsum[t] : 0;
    s[t] = orig; __syncthreads();
    for (int o = 1; o < 128; o <<= 1) {
        int v = (t >= o) ? s[t - o] : 0;
        __syncthreads();
        s[t] += v;
        __syncthreads();
    }
    if (t < nb) g_bsum[t] = s[t] - orig;
}
__global__ void k_scan3(int n) {
    __shared__ int s[256];
    int base = blockIdx.x * SCAN_TILE;
    int t = threadIdx.x;
    int c[4]; int tot = 0;
#pragma unroll
    for (int k = 0; k < 4; k++) {
        int idx = base + t * 4 + k;
        c[k] = (idx < n) ? g_count[idx] : 0;
        tot += c[k];
    }
    s[t] = tot; __syncthreads();
    for (int o = 1; o < 256; o <<= 1) {
        int v = (t >= o) ? s[t - o] : 0;
        __syncthreads();
        s[t] += v;
        __syncthreads();
    }
    int off = g_bsum[blockIdx.x] + s[t] - tot;
#pragma unroll
    for (int k = 0; k < 4; k++) {
        int idx = base + t * 4 + k;
        if (idx < n) { g_rowstart[idx] = off; off += c[k]; }
    }
}
__global__ void k_build(const int* __restrict__ src, const int* __restrict__ dst, int E) {
    int e = blockIdx.x * blockDim.x + threadIdx.x;
    if (e >= E) return;
    int s = src[e], d = dst[e];
    float nm = g_dinv[s] * g_dinv[d];
    int pos = g_rowstart[d] + atomicAdd(&g_cursor[d], 1);
    g_perm[pos] = make_int2(s, __float_as_int(nm));
}

// ---------------- fuse W4/b4 with Wl/bl ----------------
__global__ void k_fuse(const float* __restrict__ W4, const float* __restrict__ b4,
                       const float* __restrict__ Wl, const float* __restrict__ bl) {
    int k = threadIdx.x;   // 0..63
    int j = blockIdx.x;    // 0..1
    float a = 0.0f;
#pragma unroll
    for (int m = 0; m < 10; m++) a += Wl[j * 10 + m] * W4[m * 64 + k];
    g_wf[j * 64 + k] = a;
    if (k == 0) {
        float bb = bl[j];
#pragma unroll
        for (int m = 0; m < 10; m++) bb += Wl[j * 10 + m] * b4[m];
        g_bf[j] = bb;
    }
}

// ---------------- Layer 1: gather x (w8) + transform 8->16 relu -> g_h1 ----------------
__global__ void __launch_bounds__(256) k_layer1(const float* __restrict__ x,
                                                const float* __restrict__ W1,
                                                const float* __restrict__ b1, int n) {
    __shared__ float sWt[8 * 16];     // k-major: sWt[k*16+j] = W1[j*8+k]
    __shared__ float sb[16];
    __shared__ float stage[8][8];
    int tid = threadIdx.x;
    for (int i = tid; i < 128; i += 256) sWt[i] = W1[(i & 15) * 8 + (i >> 4)];
    if (tid < 16) sb[tid] = b1[tid];
    __syncthreads();

    int w = (blockIdx.x * 256 + tid) >> 5;
    int lane = tid & 31;
    int wl = tid >> 5;
    if (w >= n) return;
    int base = g_rowstart[w], cnt = g_count[w];
    float dv = g_dinv[w];
    int g = lane >> 3, sub = lane & 7;
    float acc = (g == 0) ? __ldg(&x[w * 8 + sub]) * dv * dv : 0.0f;
#pragma unroll 4
    for (int i = g; i < cnt; i += 4) {
        int2 p = g_perm[base + i];
        acc = fmaf(__int_as_float(p.y), __ldg(&x[p.x * 8 + sub]), acc);
    }
    acc += __shfl_xor_sync(0xffffffffu, acc, 8);
    acc += __shfl_xor_sync(0xffffffffu, acc, 16);
    if (lane < 8) stage[wl][lane] = acc;
    __syncwarp();
    if (lane < 16) {
        float o = sb[lane];
#pragma unroll
        for (int k = 0; k < 8; k++) o = fmaf(stage[wl][k], sWt[k * 16 + lane], o);
        g_h1[w * 16 + lane] = fmaxf(o, 0.0f);
    }
}

// ---------------- Layer 2: gather h1 (w16) + transform 16->64 relu -> g_h2 fp16 ----------------
__global__ void __launch_bounds__(256) k_layer2(const float* __restrict__ W2,
                                                const float* __restrict__ b2, int n) {
    __shared__ float sWt[16 * 64];    // sWt[k*64+j] = W2[j*16+k]
    __shared__ float sb[64];
    __shared__ float stage[8][16];
    int tid = threadIdx.x;
    for (int i = tid; i < 1024; i += 256) sWt[i] = W2[(i & 63) * 16 + (i >> 6)];
    if (tid < 64) sb[tid] = b2[tid];
    __syncthreads();

    int w = (blockIdx.x * 256 + tid) >> 5;
    int lane = tid & 31;
    int wl = tid >> 5;
    if (w >= n) return;
    int base = g_rowstart[w], cnt = g_count[w];
    float dv = g_dinv[w];
    int g = lane >> 4, sub = lane & 15;
    float acc = (g == 0) ? g_h1[w * 16 + sub] * dv * dv : 0.0f;
#pragma unroll 4
    for (int i = g; i < cnt; i += 2) {
        int2 p = g_perm[base + i];
        acc = fmaf(__int_as_float(p.y), g_h1[p.x * 16 + sub], acc);
    }
    acc += __shfl_xor_sync(0xffffffffu, acc, 16);
    if (lane < 16) stage[wl][lane] = acc;
    __syncwarp();
    float a0 = sb[2 * lane], a1 = sb[2 * lane + 1];
    const float2* sW2 = reinterpret_cast<const float2*>(sWt);
#pragma unroll
    for (int k = 0; k < 16; k++) {
        float s = stage[wl][k];
        float2 wv = sW2[k * 32 + lane];
        a0 = fmaf(s, wv.x, a0);
        a1 = fmaf(s, wv.y, a1);
    }
    g_h2[w * 32 + lane] = __floats2half2_rn(fmaxf(a0, 0.0f), fmaxf(a1, 0.0f));
}

// ---------------- Layer 3: gather h2 fp16 (w64) + transform 64->64 relu + project Wf -> g_t ----------------
__global__ void __launch_bounds__(256) k_layer3(const float* __restrict__ W3,
                                                const float* __restrict__ b3, int n) {
    __shared__ float sWt[64 * 64];    // sWt[k*64+j] = W3[j*64+k]
    __shared__ float sb[64];
    __shared__ float stage[8][64];
    int tid = threadIdx.x;
    for (int i = tid; i < 4096; i += 256) sWt[i] = W3[(i & 63) * 64 + (i >> 6)];
    if (tid < 64) sb[tid] = b3[tid];
    __syncthreads();

    int w = (blockIdx.x * 256 + tid) >> 5;
    int lane = tid & 31;
    int wl = tid >> 5;
    if (w >= n) return;
    int base = g_rowstart[w], cnt = g_count[w];
    float dv = g_dinv[w];
    float2 self = __half22float2(g_h2[w * 32 + lane]);
    float2 acc = make_float2(self.x * dv * dv, self.y * dv * dv);
    int i = 0;
    for (; i + 8 <= cnt; i += 8) {
        int2 p[8];
        float2 vv[8];
#pragma unroll
        for (int k = 0; k < 8; k++) p[k] = g_perm[base + i + k];
#pragma unroll
        for (int k = 0; k < 8; k++) vv[k] = __half22float2(g_h2[p[k].x * 32 + lane]);
#pragma unroll
        for (int k = 0; k < 8; k++) {
            float nm = __int_as_float(p[k].y);
            acc.x = fmaf(nm, vv[k].x, acc.x);
            acc.y = fmaf(nm, vv[k].y, acc.y);
        }
    }
    for (; i < cnt; i++) {
        int2 p = g_perm[base + i];
        float2 v0 = __half22float2(g_h2[p.x * 32 + lane]);
        float nm = __int_as_float(p.y);
        acc.x = fmaf(nm, v0.x, acc.x);
        acc.y = fmaf(nm, v0.y, acc.y);
    }
    stage[wl][2 * lane] = acc.x;
    stage[wl][2 * lane + 1] = acc.y;
    __syncwarp();
    // transform 64->64 (+bias, relu)
    float a0 = sb[2 * lane], a1 = sb[2 * lane + 1];
    const float2* sW2 = reinterpret_cast<const float2*>(sWt);
#pragma unroll
    for (int k = 0; k < 64; k++) {
        float s = stage[wl][k];
        float2 wv = sW2[k * 32 + lane];
        a0 = fmaf(s, wv.x, a0);
        a1 = fmaf(s, wv.y, a1);
    }
    a0 = fmaxf(a0, 0.0f);
    a1 = fmaxf(a1, 0.0f);
    // project with fused Wf [2,64]
    float t0 = a0 * g_wf[2 * lane]      + a1 * g_wf[2 * lane + 1];
    float t1 = a0 * g_wf[64 + 2 * lane] + a1 * g_wf[64 + 2 * lane + 1];
#pragma unroll
    for (int o = 16; o > 0; o >>= 1) {
        t0 += __shfl_down_sync(0xffffffffu, t0, o);
        t1 += __shfl_down_sync(0xffffffffu, t1, o);
    }
    if (lane == 0) g_t[w] = make_float2(t0, t1);
}

// ---------------- final: out[v] = bf + dinv^2*t[v] + sum nm*t[src] ----------------
__global__ void __launch_bounds__(256) k_out(float* __restrict__ out, int n) {
    int v = blockIdx.x * blockDim.x + threadIdx.x;
    if (v >= n) return;
    int base = g_rowstart[v], cnt = g_count[v];
    float dv = g_dinv[v];
    float2 self = g_t[v];
    float2 acc;
    acc.x = g_bf[0] + dv * dv * self.x;
    acc.y = g_bf[1] + dv * dv * self.y;
    int i = 0;
    for (; i + 8 <= cnt; i += 8) {
        int2 p[8];
        float2 vv[8];
#pragma unroll
        for (int k = 0; k < 8; k++) p[k] = g_perm[base + i + k];
#pragma unroll
        for (int k = 0; k < 8; k++) vv[k] = g_t[p[k].x];
#pragma unroll
        for (int k = 0; k < 8; k++) {
            float nm = __int_as_float(p[k].y);
            acc.x = fmaf(nm, vv[k].x, acc.x);
            acc.y = fmaf(nm, vv[k].y, acc.y);
        }
    }
    for (; i < cnt; i++) {
        int2 p = g_perm[base + i];
        float2 s = g_t[p.x];
        float nm = __int_as_float(p.y);
        acc.x = fmaf(nm, s.x, acc.x);
        acc.y = fmaf(nm, s.y, acc.y);
    }
    reinterpret_cast<float2*>(out)[v] = acc;
}

extern "C" void kernel_launch(void* const* d_in, const int* in_sizes, int n_in,
                              void* d_out, int out_size) {
    const float* x  = (const float*)d_in[0];
    const int*   ei = (const int*)d_in[1];
    const float* W1 = (const float*)d_in[2];
    const float* b1 = (const float*)d_in[3];
    const float* W2 = (const float*)d_in[4];
    const float* b2 = (const float*)d_in[5];
    const float* W3 = (const float*)d_in[6];
    const float* b3 = (const float*)d_in[7];
    const float* W4 = (const float*)d_in[8];
    const float* b4 = (const float*)d_in[9];
    const float* Wl = (const float*)d_in[10];
    const float* bl = (const float*)d_in[11];
    float* out = (float*)d_out;

    int n = in_sizes[0] / 8;   // 100000
    int E = in_sizes[1] / 2;   // 3200000
    const int* src = ei;       // edge_index[0]
    const int* dst = ei + E;   // edge_index[1]

    const int B = 256;
    auto blocks = [&](long total) { return (int)((total + B - 1) / B); };
    int nscan = (n + SCAN_TILE - 1) / SCAN_TILE;

    // CSR build
    k_zero<<<blocks(n), B>>>(n);
    k_count<<<blocks(E), B>>>(dst, E);
    k_dinv<<<blocks(n), B>>>(n);
    k_scan1<<<nscan, 256>>>(n);
    k_scan2<<<1, 128>>>(nscan);
    k_scan3<<<nscan, 256>>>(n);
    k_build<<<blocks(E), B>>>(src, dst, E);
    k_fuse<<<2, 64>>>(W4, b4, Wl, bl);

    // Fused layers
    k_layer1<<<blocks((long)n * 32), B>>>(x, W1, b1, n);
    k_layer2<<<blocks((long)n * 32), B>>>(W2, b2, n);
    k_layer3<<<blocks((long)n * 32), B>>>(W3, b3, n);
    k_out<<<blocks(n), B>>>(out, n);
}

// round 7
// speedup vs baseline: 1.8634x; 1.1053x over previous
#include <cuda_runtime.h>
#include <cuda_fp16.h>

// Problem constants (fixed by the dataset)
#define NN 100000
#define EE 3200000
#define SCAN_TILE 1024

// Scratch (device globals; no allocation allowed). Kernels reference these
// directly — kernel_launch makes no runtime-API calls besides launches.
__device__ float g_dinv[NN];                      // 1/sqrt(deg)
__device__ int   g_count[NN];                     // per-dst in-degree (excl self loop)
__device__ int   g_rowstart[NN];                  // CSR offsets; after build holds row END
__device__ int   g_bsum[128];                     // scan block sums
__device__ int   g_idx[EE];                       // src indices, dst-sorted
__device__ __align__(16) __half2 g_xs[NN * 4];    // x~ = dinv*x, fp16 (8 per node)
__device__ __align__(16) __half2 g_h1[NN * 8];    // h1~ = dinv*h1, fp16 (16 per node)
__device__ __align__(16) __half2 g_h2[NN * 32];   // h2~ = dinv*h2, fp16 (64 per node)
__device__ __align__(16) float2  g_t[NN];         // t~ = dinv*t
__device__ float g_wf[2 * 64];                    // fused Wl@W4
__device__ float g_bf[2];                         // fused Wl@b4 + bl

// ---------------- CSR build ----------------
__global__ void k_zero(int n) {
    int v = blockIdx.x * blockDim.x + threadIdx.x;
    if (v < n) g_count[v] = 0;
}
__global__ void k_count(const int* __restrict__ dst, int E) {
    int e = blockIdx.x * blockDim.x + threadIdx.x;
    if (e < E) atomicAdd(&g_count[dst[e]], 1);
}
__global__ void k_dinv(int n) {
    int v = blockIdx.x * blockDim.x + threadIdx.x;
    if (v < n) g_dinv[v] = rsqrtf((float)(g_count[v] + 1));   // +1: self loop
}
__global__ void k_scan1(int n) {
    __shared__ int s[256];
    int base = blockIdx.x * SCAN_TILE;
    int t = threadIdx.x;
    int sum = 0;
    for (int i = t; i < SCAN_TILE; i += 256) {
        int idx = base + i;
        if (idx < n) sum += g_count[idx];
    }
    s[t] = sum; __syncthreads();
    for (int o = 128; o > 0; o >>= 1) { if (t < o) s[t] += s[t + o]; __syncthreads(); }
    if (t == 0) g_bsum[blockIdx.x] = s[0];
}
__global__ void k_scan2(int nb) {
    __shared__ int s[128];
    int t = threadIdx.x;
    int orig = (t < nb) ? g_bsum[t] : 0;
    s[t] = orig; __syncthreads();
    for (int o = 1; o < 128; o <<= 1) {
        int v = (t >= o) ? s[t - o] : 0;
        __syncthreads();
        s[t] += v;
        __syncthreads();
    }
    if (t < nb) g_bsum[t] = s[t] - orig;
}
__global__ void k_scan3(int n) {
    __shared__ int s[256];
    int base = blockIdx.x * SCAN_TILE;
    int t = threadIdx.x;
    int c[4]; int tot = 0;
#pragma unroll
    for (int k = 0; k < 4; k++) {
        int idx = base + t * 4 + k;
        c[k] = (idx < n) ? g_count[idx] : 0;
        tot += c[k];
    }
    s[t] = tot; __syncthreads();
    for (int o = 1; o < 256; o <<= 1) {
        int v = (t >= o) ? s[t - o] : 0;
        __syncthreads();
        s[t] += v;
        __syncthreads();
    }
    int off = g_bsum[blockIdx.x] + s[t] - tot;
#pragma unroll
    for (int k = 0; k < 4; k++) {
        int idx = base + t * 4 + k;
        if (idx < n) { g_rowstart[idx] = off; off += c[k]; }
    }
}
// place src indices dst-sorted; rowstart post-incremented to row END
__global__ void k_build(const int* __restrict__ src, const int* __restrict__ dst, int E) {
    int e = blockIdx.x * blockDim.x + threadIdx.x;
    if (e >= E) return;
    int pos = atomicAdd(&g_rowstart[dst[e]], 1);
    g_idx[pos] = src[e];
}

// ---------------- fuse W4/b4 with Wl/bl ----------------
__global__ void k_fuse(const float* __restrict__ W4, const float* __restrict__ b4,
                       const float* __restrict__ Wl, const float* __restrict__ bl) {
    int k = threadIdx.x;   // 0..63
    int j = blockIdx.x;    // 0..1
    float a = 0.0f;
#pragma unroll
    for (int m = 0; m < 10; m++) a += Wl[j * 10 + m] * W4[m * 64 + k];
    g_wf[j * 64 + k] = a;
    if (k == 0) {
        float bb = bl[j];
#pragma unroll
        for (int m = 0; m < 10; m++) bb += Wl[j * 10 + m] * b4[m];
        g_bf[j] = bb;
    }
}

// ---------------- x~ = dinv * x, fp16 ----------------
__global__ void k_xs(const float* __restrict__ x, int n) {
    int i = blockIdx.x * blockDim.x + threadIdx.x;
    if (i >= n * 4) return;
    int v = i >> 2;
    float dv = g_dinv[v];
    float2 xv = reinterpret_cast<const float2*>(x)[i];
    g_xs[i] = __floats2half2_rn(dv * xv.x, dv * xv.y);
}

// ---- Layer 1: plain gather of x~ (8 edges x 4 chunks per warp) + 8->16 relu -> h1~ fp16 ----
__global__ void __launch_bounds__(256) k_layer1(const float* __restrict__ W1,
                                                const float* __restrict__ b1, int n) {
    __shared__ float sWt[8 * 16];     // k-major: sWt[k*16+j] = W1[j*8+k]
    __shared__ float sb[16];
    __shared__ float stage[8][8];
    int tid = threadIdx.x;
    if (tid < 128) sWt[tid] = W1[(tid & 15) * 8 + (tid >> 4)];
    if (tid < 16) sb[tid] = b1[tid];
    __syncthreads();

    int w = (blockIdx.x * 256 + tid) >> 5;
    int lane = tid & 31;
    int wl = tid >> 5;
    if (w >= n) return;
    int end = g_rowstart[w], cnt = g_count[w], base = end - cnt;
    float dv = g_dinv[w];
    int e = lane >> 2, c = lane & 3;     // lane = e*4 + c
    float2 acc = (e == 0) ? __half22float2(g_xs[w * 4 + c]) : make_float2(0.f, 0.f);
#pragma unroll 4
    for (int i = e; i < cnt; i += 8) {
        int s = g_idx[base + i];
        float2 v = __half22float2(g_xs[s * 4 + c]);
        acc.x += v.x; acc.y += v.y;
    }
#pragma unroll
    for (int o = 4; o <= 16; o <<= 1) {   // reduce over e (lane bits 2..4)
        acc.x += __shfl_xor_sync(0xffffffffu, acc.x, o);
        acc.y += __shfl_xor_sync(0xffffffffu, acc.y, o);
    }
    if (lane < 4) { stage[wl][2 * lane] = dv * acc.x; stage[wl][2 * lane + 1] = dv * acc.y; }
    __syncwarp();
    if (lane < 8) {
        const float2* sW2 = reinterpret_cast<const float2*>(sWt);
        float a0 = sb[2 * lane], a1 = sb[2 * lane + 1];
#pragma unroll
        for (int k = 0; k < 8; k++) {
            float s = stage[wl][k];
            float2 wv = sW2[k * 8 + lane];
            a0 = fmaf(s, wv.x, a0);
            a1 = fmaf(s, wv.y, a1);
        }
        g_h1[w * 8 + lane] = __floats2half2_rn(dv * fmaxf(a0, 0.f), dv * fmaxf(a1, 0.f));
    }
}

// ---- Layer 2: gather h1~ (4 edges x 8 chunks per warp) + 16->64 relu -> h2~ fp16 ----
__global__ void __launch_bounds__(256) k_layer2(const float* __restrict__ W2,
                                                const float* __restrict__ b2, int n) {
    __shared__ float sWt[16 * 64];    // sWt[k*64+j] = W2[j*16+k]
    __shared__ float sb[64];
    __shared__ float stage[8][16];
    int tid = threadIdx.x;
    for (int i = tid; i < 1024; i += 256) sWt[i] = W2[(i & 63) * 16 + (i >> 6)];
    if (tid < 64) sb[tid] = b2[tid];
    __syncthreads();

    int w = (blockIdx.x * 256 + tid) >> 5;
    int lane = tid & 31;
    int wl = tid >> 5;
    if (w >= n) return;
    int end = g_rowstart[w], cnt = g_count[w], base = end - cnt;
    float dv = g_dinv[w];
    int e = lane >> 3, c = lane & 7;     // lane = e*8 + c
    float2 acc = (e == 0) ? __half22float2(g_h1[w * 8 + c]) : make_float2(0.f, 0.f);
#pragma unroll 4
    for (int i = e; i < cnt; i += 4) {
        int s = g_idx[base + i];
        float2 v = __half22float2(g_h1[s * 8 + c]);
        acc.x += v.x; acc.y += v.y;
    }
#pragma unroll
    for (int o = 8; o <= 16; o <<= 1) {   // reduce over e (lane bits 3..4)
        acc.x += __shfl_xor_sync(0xffffffffu, acc.x, o);
        acc.y += __shfl_xor_sync(0xffffffffu, acc.y, o);
    }
    if (lane < 8) { stage[wl][2 * lane] = dv * acc.x; stage[wl][2 * lane + 1] = dv * acc.y; }
    __syncwarp();
    float a0 = sb[2 * lane], a1 = sb[2 * lane + 1];
    const float2* sW2 = reinterpret_cast<const float2*>(sWt);
#pragma unroll
    for (int k = 0; k < 16; k++) {
        float s = stage[wl][k];
        float2 wv = sW2[k * 32 + lane];
        a0 = fmaf(s, wv.x, a0);
        a1 = fmaf(s, wv.y, a1);
    }
    g_h2[w * 32 + lane] = __floats2half2_rn(dv * fmaxf(a0, 0.f), dv * fmaxf(a1, 0.f));
}

// ---- Layer 3: gather h2~ (warp/node) + 64->64 relu + project Wf -> t~ ----
__global__ void __launch_bounds__(256) k_layer3(const float* __restrict__ W3,
                                                const float* __restrict__ b3, int n) {
    __shared__ float sWt[64 * 64];    // sWt[k*64+j] = W3[j*64+k]
    __shared__ float sb[64];
    __shared__ float stage[8][64];
    int tid = threadIdx.x;
    for (int i = tid; i < 4096; i += 256) sWt[i] = W3[(i & 63) * 64 + (i >> 6)];
    if (tid < 64) sb[tid] = b3[tid];
    __syncthreads();

    int w = (blockIdx.x * 256 + tid) >> 5;
    int lane = tid & 31;
    int wl = tid >> 5;
    if (w >= n) return;
    int end = g_rowstart[w], cnt = g_count[w], base = end - cnt;
    float dv = g_dinv[w];
    float2 acc = __half22float2(g_h2[w * 32 + lane]);   // self term (already dinv-scaled)
    int i = 0;
    for (; i + 8 <= cnt; i += 8) {
        int s[8];
        float2 vv[8];
#pragma unroll
        for (int k = 0; k < 8; k++) s[k] = g_idx[base + i + k];
#pragma unroll
        for (int k = 0; k < 8; k++) vv[k] = __half22float2(g_h2[s[k] * 32 + lane]);
#pragma unroll
        for (int k = 0; k < 8; k++) { acc.x += vv[k].x; acc.y += vv[k].y; }
    }
    for (; i < cnt; i++) {
        int s = g_idx[base + i];
        float2 v = __half22float2(g_h2[s * 32 + lane]);
        acc.x += v.x; acc.y += v.y;
    }
    stage[wl][2 * lane] = dv * acc.x;
    stage[wl][2 * lane + 1] = dv * acc.y;
    __syncwarp();
    // transform 64->64 (+bias, relu)
    float a0 = sb[2 * lane], a1 = sb[2 * lane + 1];
    const float2* sW2 = reinterpret_cast<const float2*>(sWt);
#pragma unroll
    for (int k = 0; k < 64; k++) {
        float s = stage[wl][k];
        float2 wv = sW2[k * 32 + lane];
        a0 = fmaf(s, wv.x, a0);
        a1 = fmaf(s, wv.y, a1);
    }
    a0 = fmaxf(a0, 0.0f);
    a1 = fmaxf(a1, 0.0f);
    // project with fused Wf [2,64], then pre-scale by dinv for the final pass
    float t0 = a0 * g_wf[2 * lane]      + a1 * g_wf[2 * lane + 1];
    float t1 = a0 * g_wf[64 + 2 * lane] + a1 * g_wf[64 + 2 * lane + 1];
#pragma unroll
    for (int o = 16; o > 0; o >>= 1) {
        t0 += __shfl_down_sync(0xffffffffu, t0, o);
        t1 += __shfl_down_sync(0xffffffffu, t1, o);
    }
    if (lane == 0) g_t[w] = make_float2(dv * t0, dv * t1);
}

// ---------------- final: out[v] = bf + dinv[v]*(sum t~[s] + t~[v]) ----------------
__global__ void __launch_bounds__(256) k_out(float* __restrict__ out, int n) {
    int v = blockIdx.x * blockDim.x + threadIdx.x;
    if (v >= n) return;
    int end = g_rowstart[v], cnt = g_count[v], base = end - cnt;
    float dv = g_dinv[v];
    float2 acc = g_t[v];
    int i = 0;
    for (; i + 8 <= cnt; i += 8) {
        int s[8];
        float2 vv[8];
#pragma unroll
        for (int k = 0; k < 8; k++) s[k] = g_idx[base + i + k];
#pragma unroll
        for (int k = 0; k < 8; k++) vv[k] = g_t[s[k]];
#pragma unroll
        for (int k = 0; k < 8; k++) { acc.x += vv[k].x; acc.y += vv[k].y; }
    }
    for (; i < cnt; i++) {
        float2 s = g_t[g_idx[base + i]];
        acc.x += s.x; acc.y += s.y;
    }
    float2 o;
    o.x = g_bf[0] + dv * acc.x;
    o.y = g_bf[1] + dv * acc.y;
    reinterpret_cast<float2*>(out)[v] = o;
}

extern "C" void kernel_launch(void* const* d_in, const int* in_sizes, int n_in,
                              void* d_out, int out_size) {
    const float* x  = (const float*)d_in[0];
    const int*   ei = (const int*)d_in[1];
    const float* W1 = (const float*)d_in[2];
    const float* b1 = (const float*)d_in[3];
    const float* W2 = (const float*)d_in[4];
    const float* b2 = (const float*)d_in[5];
    const float* W3 = (const float*)d_in[6];
    const float* b3 = (const float*)d_in[7];
    const float* W4 = (const float*)d_in[8];
    const float* b4 = (const float*)d_in[9];
    const float* Wl = (const float*)d_in[10];
    const float* bl = (const float*)d_in[11];
    float* out = (float*)d_out;

    int n = in_sizes[0] / 8;   // 100000
    int E = in_sizes[1] / 2;   // 3200000
    const int* src = ei;       // edge_index[0]
    const int* dst = ei + E;   // edge_index[1]

    const int B = 256;
    auto blocks = [&](long total) { return (int)((total + B - 1) / B); };
    int nscan = (n + SCAN_TILE - 1) / SCAN_TILE;

    // CSR build (index-only)
    k_zero<<<blocks(n), B>>>(n);
    k_count<<<blocks(E), B>>>(dst, E);
    k_dinv<<<blocks(n), B>>>(n);
    k_scan1<<<nscan, 256>>>(n);
    k_scan2<<<1, 128>>>(nscan);
    k_scan3<<<nscan, 256>>>(n);
    k_build<<<blocks(E), B>>>(src, dst, E);
    k_fuse<<<2, 64>>>(W4, b4, Wl, bl);
    k_xs<<<blocks((long)n * 4), B>>>(x, n);

    // Fused layers (plain index-sum gathers; dinv folded into epilogues)
    k_layer1<<<blocks((long)n * 32), B>>>(W1, b1, n);
    k_layer2<<<blocks((long)n * 32), B>>>(W2, b2, n);
    k_layer3<<<blocks((long)n * 32), B>>>(W3, b3, n);
    k_out<<<blocks(n), B>>>(out, n);
}

// round 8
// speedup vs baseline: 1.8638x; 1.0002x over previous
#include <cuda_runtime.h>
#include <cuda_fp16.h>

// Problem constants (fixed by the dataset)
#define NN 100000
#define EE 3200000
#define EPAD (EE + 4 * NN)     // padded edge capacity (rows padded to multiple of 4)
#define SCAN_TILE 1024

// Scratch (device globals; no allocation allowed). Kernels reference these
// directly — kernel_launch makes no runtime-API calls besides launches.
// Feature arrays have one extra zero row (index NN) for dummy padded edges;
// it is zero-initialized at module load and never written.
__device__ float g_dinv[NN];                            // 1/sqrt(deg)
__device__ int   g_count[NN];                           // per-dst in-degree (excl self loop)
__device__ int   g_rowstart[NN];                        // padded CSR starts; after build = start+cnt
__device__ int   g_bsum[128];                           // scan block sums
__device__ int   g_idx[EPAD];                           // src indices, dst-sorted, rows padded to 4
__device__ __align__(16) __half2 g_xs[(NN + 1) * 4];    // x~ = dinv*x, fp16
__device__ __align__(16) __half2 g_h1[(NN + 1) * 8];    // h1~ = dinv*h1, fp16
__device__ __align__(16) __half2 g_h2[(NN + 1) * 32];   // h2~ = dinv*h2, fp16
__device__ __align__(16) float2  g_t[NN + 1];           // t~ = dinv*t
__device__ float g_wf[2 * 64];                          // fused Wl@W4
__device__ float g_bf[2];                               // fused Wl@b4 + bl

// ---------------- CSR build ----------------
__global__ void k_zero(int n) {
    int v = blockIdx.x * blockDim.x + threadIdx.x;
    if (v < n) g_count[v] = 0;
}
__global__ void k_count(const int* __restrict__ dst, int E4) {
    int i = blockIdx.x * blockDim.x + threadIdx.x;
    if (i >= E4) return;
    int4 d = __ldg(reinterpret_cast<const int4*>(dst) + i);
    atomicAdd(&g_count[d.x], 1);
    atomicAdd(&g_count[d.y], 1);
    atomicAdd(&g_count[d.z], 1);
    atomicAdd(&g_count[d.w], 1);
}
// scan step 1 over PADDED counts; also computes dinv
__global__ void k_scan1(int n) {
    __shared__ int s[256];
    int base = blockIdx.x * SCAN_TILE;
    int t = threadIdx.x;
    int sum = 0;
    for (int i = t; i < SCAN_TILE; i += 256) {
        int idx = base + i;
        if (idx < n) {
            int c = g_count[idx];
            g_dinv[idx] = rsqrtf((float)(c + 1));   // +1: self loop
            sum += (c + 3) & ~3;
        }
    }
    s[t] = sum; __syncthreads();
    for (int o = 128; o > 0; o >>= 1) { if (t < o) s[t] += s[t + o]; __syncthreads(); }
    if (t == 0) g_bsum[blockIdx.x] = s[0];
}
__global__ void k_scan2(int nb) {
    __shared__ int s[128];
    int t = threadIdx.x;
    int orig = (t < nb) ? g_bsum[t] : 0;
    s[t] = orig; __syncthreads();
    for (int o = 1; o < 128; o <<= 1) {
        int v = (t >= o) ? s[t - o] : 0;
        __syncthreads();
        s[t] += v;
        __syncthreads();
    }
    if (t < nb) g_bsum[t] = s[t] - orig;
}
__global__ void k_scan3(int n) {
    __shared__ int s[256];
    int base = blockIdx.x * SCAN_TILE;
    int t = threadIdx.x;
    int c[4]; int tot = 0;
#pragma unroll
    for (int k = 0; k < 4; k++) {
        int idx = base + t * 4 + k;
        c[k] = (idx < n) ? ((g_count[idx] + 3) & ~3) : 0;
        tot += c[k];
    }
    s[t] = tot; __syncthreads();
    for (int o = 1; o < 256; o <<= 1) {
        int v = (t >= o) ? s[t - o] : 0;
        __syncthreads();
        s[t] += v;
        __syncthreads();
    }
    int off = g_bsum[blockIdx.x] + s[t] - tot;
#pragma unroll
    for (int k = 0; k < 4; k++) {
        int idx = base + t * 4 + k;
        if (idx < n) { g_rowstart[idx] = off; off += c[k]; }
    }
}
// fill dummy slots [start+cnt, start+cnt4) with index n (zero feature row)
__global__ void k_pad(int n) {
    int v = blockIdx.x * blockDim.x + threadIdx.x;
    if (v >= n) return;
    int start = g_rowstart[v], cnt = g_count[v];
    int cnt4 = (cnt + 3) & ~3;
    for (int j = cnt; j < cnt4; j++) g_idx[start + j] = n;
}
// place src indices; rowstart post-incremented to start+cnt
__global__ void k_build(const int* __restrict__ src, const int* __restrict__ dst, int E4) {
    int i = blockIdx.x * blockDim.x + threadIdx.x;
    if (i >= E4) return;
    int4 s = __ldg(reinterpret_cast<const int4*>(src) + i);
    int4 d = __ldg(reinterpret_cast<const int4*>(dst) + i);
    g_idx[atomicAdd(&g_rowstart[d.x], 1)] = s.x;
    g_idx[atomicAdd(&g_rowstart[d.y], 1)] = s.y;
    g_idx[atomicAdd(&g_rowstart[d.z], 1)] = s.z;
    g_idx[atomicAdd(&g_rowstart[d.w], 1)] = s.w;
}

// ---------------- x~ = dinv*x (fp16) + fused Wf/bf build ----------------
__global__ void k_xsfuse(const float* __restrict__ x,
                         const float* __restrict__ W4, const float* __restrict__ b4,
                         const float* __restrict__ Wl, const float* __restrict__ bl, int n) {
    int i = blockIdx.x * blockDim.x + threadIdx.x;
    if (blockIdx.x == 0 && threadIdx.x < 128) {
        int k = threadIdx.x & 63, j = threadIdx.x >> 6;
        float a = 0.0f;
#pragma unroll
        for (int m = 0; m < 10; m++) a += Wl[j * 10 + m] * W4[m * 64 + k];
        g_wf[j * 64 + k] = a;
        if (k == 0) {
            float bb = bl[j];
#pragma unroll
            for (int m = 0; m < 10; m++) bb += Wl[j * 10 + m] * b4[m];
            g_bf[j] = bb;
        }
    }
    if (i >= n * 2) return;
    int v = i >> 1;
    float dv = g_dinv[v];
    float4 xv = __ldg(reinterpret_cast<const float4*>(x) + i);
    g_xs[i * 2 + 0] = __floats2half2_rn(dv * xv.x, dv * xv.y);
    g_xs[i * 2 + 1] = __floats2half2_rn(dv * xv.z, dv * xv.w);
}

// ---- Layer 1: gather x~ (8 edges x 4 chunks per warp) + 8->16 relu -> h1~ fp16 ----
__global__ void __launch_bounds__(256) k_layer1(const float* __restrict__ W1,
                                                const float* __restrict__ b1, int n) {
    __shared__ float sWt[8 * 16];     // k-major: sWt[k*16+j] = W1[j*8+k]
    __shared__ float sb[16];
    __shared__ float stage[8][8];
    int tid = threadIdx.x;
    if (tid < 128) sWt[tid] = W1[(tid & 15) * 8 + (tid >> 4)];
    if (tid < 16) sb[tid] = b1[tid];
    __syncthreads();

    int w = (blockIdx.x * 256 + tid) >> 5;
    int lane = tid & 31;
    int wl = tid >> 5;
    if (w >= n) return;
    int end = g_rowstart[w], cnt = g_count[w], base = end - cnt;
    int cnt4 = (cnt + 3) & ~3;
    float dv = g_dinv[w];
    int e = lane >> 2, c = lane & 3;     // lane = e*4 + c
    float2 acc = (e == 0) ? __half22float2(__ldg(&g_xs[w * 4 + c])) : make_float2(0.f, 0.f);
#pragma unroll 2
    for (int i = e; i < cnt4; i += 8) {
        int s = __ldg(&g_idx[base + i]);
        float2 v = __half22float2(__ldg(&g_xs[s * 4 + c]));
        acc.x += v.x; acc.y += v.y;
    }
#pragma unroll
    for (int o = 4; o <= 16; o <<= 1) {   // reduce over e (lane bits 2..4)
        acc.x += __shfl_xor_sync(0xffffffffu, acc.x, o);
        acc.y += __shfl_xor_sync(0xffffffffu, acc.y, o);
    }
    if (lane < 4) { stage[wl][2 * lane] = dv * acc.x; stage[wl][2 * lane + 1] = dv * acc.y; }
    __syncwarp();
    if (lane < 8) {
        const float2* sW2 = reinterpret_cast<const float2*>(sWt);
        float a0 = sb[2 * lane], a1 = sb[2 * lane + 1];
#pragma unroll
        for (int k = 0; k < 8; k++) {
            float s = stage[wl][k];
            float2 wv = sW2[k * 8 + lane];
            a0 = fmaf(s, wv.x, a0);
            a1 = fmaf(s, wv.y, a1);
        }
        g_h1[w * 8 + lane] = __floats2half2_rn(dv * fmaxf(a0, 0.f), dv * fmaxf(a1, 0.f));
    }
}

// ---- Layer 2: gather h1~ (4 edges x 8 chunks per warp, tail-free) + 16->64 relu -> h2~ ----
__global__ void __launch_bounds__(256) k_layer2(const float* __restrict__ W2,
                                                const float* __restrict__ b2, int n) {
    __shared__ float sWt[16 * 64];    // sWt[k*64+j] = W2[j*16+k]
    __shared__ float sb[64];
    __shared__ float stage[8][16];
    int tid = threadIdx.x;
    for (int i = tid; i < 1024; i += 256) sWt[i] = W2[(i & 63) * 16 + (i >> 6)];
    if (tid < 64) sb[tid] = b2[tid];
    __syncthreads();

    int w = (blockIdx.x * 256 + tid) >> 5;
    int lane = tid & 31;
    int wl = tid >> 5;
    if (w >= n) return;
    int end = g_rowstart[w], cnt = g_count[w], base = end - cnt;
    int cnt4 = (cnt + 3) & ~3;
    float dv = g_dinv[w];
    int e = lane >> 3, c = lane & 7;     // lane = e*8 + c
    float2 acc = (e == 0) ? __half22float2(__ldg(&g_h1[w * 8 + c])) : make_float2(0.f, 0.f);
#pragma unroll 2
    for (int i = e; i < cnt4; i += 4) {   // cnt4 % 4 == 0: uniform trips
        int s = __ldg(&g_idx[base + i]);
        float2 v = __half22float2(__ldg(&g_h1[s * 8 + c]));
        acc.x += v.x; acc.y += v.y;
    }
#pragma unroll
    for (int o = 8; o <= 16; o <<= 1) {   // reduce over e (lane bits 3..4)
        acc.x += __shfl_xor_sync(0xffffffffu, acc.x, o);
        acc.y += __shfl_xor_sync(0xffffffffu, acc.y, o);
    }
    if (lane < 8) { stage[wl][2 * lane] = dv * acc.x; stage[wl][2 * lane + 1] = dv * acc.y; }
    __syncwarp();
    float a0 = sb[2 * lane], a1 = sb[2 * lane + 1];
    const float2* sW2 = reinterpret_cast<const float2*>(sWt);
#pragma unroll
    for (int k = 0; k < 16; k++) {
        float s = stage[wl][k];
        float2 wv = sW2[k * 32 + lane];
        a0 = fmaf(s, wv.x, a0);
        a1 = fmaf(s, wv.y, a1);
    }
    g_h2[w * 32 + lane] = __floats2half2_rn(dv * fmaxf(a0, 0.f), dv * fmaxf(a1, 0.f));
}

// ---- Layer 3: gather h2~ (warp/node, int4 idx) + 64->64 relu + project Wf -> t~ ----
__global__ void __launch_bounds__(256) k_layer3(const float* __restrict__ W3,
                                                const float* __restrict__ b3, int n) {
    __shared__ float sWt[64 * 64];    // sWt[k*64+j] = W3[j*64+k]
    __shared__ float sb[64];
    __shared__ float stage[8][64];
    int tid = threadIdx.x;
    for (int i = tid; i < 4096; i += 256) sWt[i] = W3[(i & 63) * 64 + (i >> 6)];
    if (tid < 64) sb[tid] = b3[tid];
    __syncthreads();

    int w = (blockIdx.x * 256 + tid) >> 5;
    int lane = tid & 31;
    int wl = tid >> 5;
    if (w >= n) return;
    int end = g_rowstart[w], cnt = g_count[w], base = end - cnt;
    int cnt4 = (cnt + 3) & ~3;
    float dv = g_dinv[w];
    const int4* ip = reinterpret_cast<const int4*>(g_idx + base);   // base % 4 == 0
    float2 acc0 = __half22float2(__ldg(&g_h2[w * 32 + lane]));      // self term
    float2 acc1 = make_float2(0.f, 0.f);
    int i = 0;
    for (; i + 8 <= cnt4; i += 8) {
        int4 a = __ldg(ip + (i >> 2));
        int4 b = __ldg(ip + (i >> 2) + 1);
        float2 v0 = __half22float2(__ldg(&g_h2[a.x * 32 + lane]));
        float2 v1 = __half22float2(__ldg(&g_h2[a.y * 32 + lane]));
        float2 v2 = __half22float2(__ldg(&g_h2[a.z * 32 + lane]));
        float2 v3 = __half22float2(__ldg(&g_h2[a.w * 32 + lane]));
        float2 v4 = __half22float2(__ldg(&g_h2[b.x * 32 + lane]));
        float2 v5 = __half22float2(__ldg(&g_h2[b.y * 32 + lane]));
        float2 v6 = __half22float2(__ldg(&g_h2[b.z * 32 + lane]));
        float2 v7 = __half22float2(__ldg(&g_h2[b.w * 32 + lane]));
        acc0.x += v0.x + v1.x + v2.x + v3.x;
        acc0.y += v0.y + v1.y + v2.y + v3.y;
        acc1.x += v4.x + v5.x + v6.x + v7.x;
        acc1.y += v4.y + v5.y + v6.y + v7.y;
    }
    if (i < cnt4) {   // exactly 4 remain
        int4 a = __ldg(ip + (i >> 2));
        float2 v0 = __half22float2(__ldg(&g_h2[a.x * 32 + lane]));
        float2 v1 = __half22float2(__ldg(&g_h2[a.y * 32 + lane]));
        float2 v2 = __half22float2(__ldg(&g_h2[a.z * 32 + lane]));
        float2 v3 = __half22float2(__ldg(&g_h2[a.w * 32 + lane]));
        acc0.x += v0.x + v1.x + v2.x + v3.x;
        acc0.y += v0.y + v1.y + v2.y + v3.y;
    }
    acc0.x += acc1.x; acc0.y += acc1.y;
    stage[wl][2 * lane] = dv * acc0.x;
    stage[wl][2 * lane + 1] = dv * acc0.y;
    __syncwarp();
    // transform 64->64 (+bias, relu)
    float a0 = sb[2 * lane], a1 = sb[2 * lane + 1];
    const float2* sW2 = reinterpret_cast<const float2*>(sWt);
#pragma unroll
    for (int k = 0; k < 64; k++) {
        float s = stage[wl][k];
        float2 wv = sW2[k * 32 + lane];
        a0 = fmaf(s, wv.x, a0);
        a1 = fmaf(s, wv.y, a1);
    }
    a0 = fmaxf(a0, 0.0f);
    a1 = fmaxf(a1, 0.0f);
    // project with fused Wf [2,64], pre-scale by dinv for the final pass
    float t0 = a0 * g_wf[2 * lane]      + a1 * g_wf[2 * lane + 1];
    float t1 = a0 * g_wf[64 + 2 * lane] + a1 * g_wf[64 + 2 * lane + 1];
#pragma unroll
    for (int o = 16; o > 0; o >>= 1) {
        t0 += __shfl_down_sync(0xffffffffu, t0, o);
        t1 += __shfl_down_sync(0xffffffffu, t1, o);
    }
    if (lane == 0) g_t[w] = make_float2(dv * t0, dv * t1);
}

// ---------------- final: out[v] = bf + dinv[v]*(sum t~[s] + t~[v]) ----------------
__global__ void __launch_bounds__(256) k_out(float* __restrict__ out, int n) {
    int v = blockIdx.x * blockDim.x + threadIdx.x;
    if (v >= n) return;
    int end = g_rowstart[v], cnt = g_count[v], base = end - cnt;
    int cnt4 = (cnt + 3) & ~3;
    float dv = g_dinv[v];
    const int4* ip = reinterpret_cast<const int4*>(g_idx + base);
    float2 acc0 = g_t[v];
    float2 acc1 = make_float2(0.f, 0.f);
    int i = 0;
    for (; i + 8 <= cnt4; i += 8) {
        int4 a = __ldg(ip + (i >> 2));
        int4 b = __ldg(ip + (i >> 2) + 1);
        float2 v0 = __ldg(&g_t[a.x]);
        float2 v1 = __ldg(&g_t[a.y]);
        float2 v2 = __ldg(&g_t[a.z]);
        float2 v3 = __ldg(&g_t[a.w]);
        float2 v4 = __ldg(&g_t[b.x]);
        float2 v5 = __ldg(&g_t[b.y]);
        float2 v6 = __ldg(&g_t[b.z]);
        float2 v7 = __ldg(&g_t[b.w]);
        acc0.x += v0.x + v1.x + v2.x + v3.x;
        acc0.y += v0.y + v1.y + v2.y + v3.y;
        acc1.x += v4.x + v5.x + v6.x + v7.x;
        acc1.y += v4.y + v5.y + v6.y + v7.y;
    }
    if (i < cnt4) {
        int4 a = __ldg(ip + (i >> 2));
        float2 v0 = __ldg(&g_t[a.x]);
        float2 v1 = __ldg(&g_t[a.y]);
        float2 v2 = __ldg(&g_t[a.z]);
        float2 v3 = __ldg(&g_t[a.w]);
        acc0.x += v0.x + v1.x + v2.x + v3.x;
        acc0.y += v0.y + v1.y + v2.y + v3.y;
    }
    float2 o;
    o.x = g_bf[0] + dv * (acc0.x + acc1.x);
    o.y = g_bf[1] + dv * (acc0.y + acc1.y);
    reinterpret_cast<float2*>(out)[v] = o;
}

extern "C" void kernel_launch(void* const* d_in, const int* in_sizes, int n_in,
                              void* d_out, int out_size) {
    const float* x  = (const float*)d_in[0];
    const int*   ei = (const int*)d_in[1];
    const float* W1 = (const float*)d_in[2];
    const float* b1 = (const float*)d_in[3];
    const float* W2 = (const float*)d_in[4];
    const float* b2 = (const float*)d_in[5];
    const float* W3 = (const float*)d_in[6];
    const float* b3 = (const float*)d_in[7];
    const float* W4 = (const float*)d_in[8];
    const float* b4 = (const float*)d_in[9];
    const float* Wl = (const float*)d_in[10];
    const float* bl = (const float*)d_in[11];
    float* out = (float*)d_out;

    int n = in_sizes[0] / 8;   // 100000
    int E = in_sizes[1] / 2;   // 3200000
    const int* src = ei;       // edge_index[0]
    const int* dst = ei + E;   // edge_index[1]
    int E4 = E / 4;

    const int B = 256;
    auto blocks = [&](long total) { return (int)((total + B - 1) / B); };
    int nscan = (n + SCAN_TILE - 1) / SCAN_TILE;

    // CSR build (padded, index-only)
    k_zero<<<blocks(n), B>>>(n);
    k_count<<<blocks(E4), B>>>(dst, E4);
    k_scan1<<<nscan, 256>>>(n);
    k_scan2<<<1, 128>>>(nscan);
    k_scan3<<<nscan, 256>>>(n);
    k_pad<<<blocks(n), B>>>(n);
    k_build<<<blocks(E4), B>>>(src, dst, E4);
    k_xsfuse<<<blocks((long)n * 2), B>>>(x, W4, b4, Wl, bl, n);

    // Fused layers (plain index-sum gathers; dinv folded into epilogues)
    k_layer1<<<blocks((long)n * 32), B>>>(W1, b1, n);
    k_layer2<<<blocks((long)n * 32), B>>>(W2, b2, n);
    k_layer3<<<blocks((long)n * 32), B>>>(W3, b3, n);
    k_out<<<blocks(n), B>>>(out, n);
}

// round 10
// speedup vs baseline: 2.0141x; 1.0806x over previous
#include <cuda_runtime.h>
#include <cuda_fp16.h>

// Problem constants (fixed by the dataset)
#define NN 100000
#define EE 3200000
#define CAP 80          // fixed CSR row capacity (max degree ~59 for this dataset; guarded)

// Scratch (device globals; no allocation allowed). Zero-initialized at load.
// g_cnt starts zero and is re-zeroed by k_out at the end of every launch, so
// every call performs identical work on identical state (deterministic).
// Feature arrays have one extra zero row (index NN) targeted by pad slots.
__device__ int   g_cnt[NN];                             // per-dst in-degree
__device__ float g_dinv[NN];                            // 1/sqrt(deg+1)
__device__ int   g_idx[NN * CAP];                       // bucketed src indices
__device__ __align__(16) __half2 g_xs[(NN + 1) * 4];    // x~ = dinv*x, fp16
__device__ __align__(16) __half2 g_h1[(NN + 1) * 8];    // h1~ = dinv*h1, fp16
__device__ __align__(16) __half2 g_h2[(NN + 1) * 32];   // h2~ = dinv*h2, fp16
__device__ __align__(16) float2  g_t[NN + 1];           // t~ = dinv*t
__device__ float g_wf[2 * 64];                          // fused Wl@W4
__device__ float g_bf[2];                               // fused Wl@b4 + bl

// ---- build: count + place in ONE pass (g_cnt all-zero on entry) ----
__global__ void k_build(const int* __restrict__ src, const int* __restrict__ dst,
                        int E4, int E) {
    int i = blockIdx.x * blockDim.x + threadIdx.x;
    if (i == 0) {   // tail (E not divisible by 4) — no-op for E=3.2M
        for (int e = E4 * 4; e < E; e++) {
            int p = atomicAdd(&g_cnt[dst[e]], 1);
            if (p < CAP) g_idx[dst[e] * CAP + p] = src[e];
        }
    }
    if (i >= E4) return;
    int4 s = __ldg(reinterpret_cast<const int4*>(src) + i);
    int4 d = __ldg(reinterpret_cast<const int4*>(dst) + i);
    int p;
    p = atomicAdd(&g_cnt[d.x], 1); if (p < CAP) g_idx[d.x * CAP + p] = s.x;
    p = atomicAdd(&g_cnt[d.y], 1); if (p < CAP) g_idx[d.y * CAP + p] = s.y;
    p = atomicAdd(&g_cnt[d.z], 1); if (p < CAP) g_idx[d.z * CAP + p] = s.z;
    p = atomicAdd(&g_cnt[d.w], 1); if (p < CAP) g_idx[d.w * CAP + p] = s.w;
}

// ---- per-node: dinv + pad slots + x~ conversion; block 0 also builds Wf/bf ----
__global__ void k_node(const float* __restrict__ x,
                       const float* __restrict__ W4, const float* __restrict__ b4,
                       const float* __restrict__ Wl, const float* __restrict__ bl, int n) {
    if (blockIdx.x == 0 && threadIdx.x < 128) {
        int k = threadIdx.x & 63, j = threadIdx.x >> 6;
        float a = 0.0f;
#pragma unroll
        for (int m = 0; m < 10; m++) a += Wl[j * 10 + m] * W4[m * 64 + k];
        g_wf[j * 64 + k] = a;
        if (k == 0) {
            float bb = bl[j];
#pragma unroll
            for (int m = 0; m < 10; m++) bb += Wl[j * 10 + m] * b4[m];
            g_bf[j] = bb;
        }
    }
    int v = blockIdx.x * blockDim.x + threadIdx.x;
    if (v >= n) return;
    int cnt = g_cnt[v];
    if (cnt > CAP) { cnt = CAP; g_cnt[v] = CAP; }   // safety (never for this dataset)
    float dv = rsqrtf((float)(cnt + 1));            // +1: self loop
    g_dinv[v] = dv;
    int cnt4 = (cnt + 3) & ~3;
    if (cnt4 > CAP) cnt4 = CAP;
    for (int j = cnt; j < cnt4; j++) g_idx[v * CAP + j] = n;   // pads -> zero row
    float4 a = __ldg(reinterpret_cast<const float4*>(x) + v * 2);
    float4 b = __ldg(reinterpret_cast<const float4*>(x) + v * 2 + 1);
    g_xs[v * 4 + 0] = __floats2half2_rn(dv * a.x, dv * a.y);
    g_xs[v * 4 + 1] = __floats2half2_rn(dv * a.z, dv * a.w);
    g_xs[v * 4 + 2] = __floats2half2_rn(dv * b.x, dv * b.y);
    g_xs[v * 4 + 3] = __floats2half2_rn(dv * b.z, dv * b.w);
}

// ---- Layer 1: gather x~ (8 edges x 4 chunks per warp) + 8->16 relu -> h1~ fp16 ----
__global__ void __launch_bounds__(256) k_layer1(const float* __restrict__ W1,
                                                const float* __restrict__ b1, int n) {
    __shared__ float sWt[8 * 16];     // k-major: sWt[k*16+j] = W1[j*8+k]
    __shared__ float sb[16];
    __shared__ float stage[8][8];
    int tid = threadIdx.x;
    if (tid < 128) sWt[tid] = W1[(tid & 15) * 8 + (tid >> 4)];
    if (tid < 16) sb[tid] = b1[tid];
    __syncthreads();

    int w = (blockIdx.x * 256 + tid) >> 5;
    int lane = tid & 31;
    int wl = tid >> 5;
    if (w >= n) return;
    int cnt = g_cnt[w], base = w * CAP;
    int cnt4 = (cnt + 3) & ~3;
    float dv = g_dinv[w];
    int e = lane >> 2, c = lane & 3;     // lane = e*4 + c
    float2 acc = (e == 0) ? __half22float2(__ldg(&g_xs[w * 4 + c])) : make_float2(0.f, 0.f);
#pragma unroll 2
    for (int i = e; i < cnt4; i += 8) {
        int s = __ldg(&g_idx[base + i]);
        float2 v = __half22float2(__ldg(&g_xs[s * 4 + c]));
        acc.x += v.x; acc.y += v.y;
    }
#pragma unroll
    for (int o = 4; o <= 16; o <<= 1) {   // reduce over e (lane bits 2..4)
        acc.x += __shfl_xor_sync(0xffffffffu, acc.x, o);
        acc.y += __shfl_xor_sync(0xffffffffu, acc.y, o);
    }
    if (lane < 4) { stage[wl][2 * lane] = dv * acc.x; stage[wl][2 * lane + 1] = dv * acc.y; }
    __syncwarp();
    if (lane < 8) {
        const float2* sW2 = reinterpret_cast<const float2*>(sWt);
        float a0 = sb[2 * lane], a1 = sb[2 * lane + 1];
#pragma unroll
        for (int k = 0; k < 8; k++) {
            float s = stage[wl][k];
            float2 wv = sW2[k * 8 + lane];
            a0 = fmaf(s, wv.x, a0);
            a1 = fmaf(s, wv.y, a1);
        }
        g_h1[w * 8 + lane] = __floats2half2_rn(dv * fmaxf(a0, 0.f), dv * fmaxf(a1, 0.f));
    }
}

// ---- Layer 2: gather h1~ (4 edges x 8 chunks per warp) + 16->64 relu -> h2~ ----
__global__ void __launch_bounds__(256) k_layer2(const float* __restrict__ W2,
                                                const float* __restrict__ b2, int n) {
    __shared__ float sWt[16 * 64];    // sWt[k*64+j] = W2[j*16+k]
    __shared__ float sb[64];
    __shared__ float stage[8][16];
    int tid = threadIdx.x;
    for (int i = tid; i < 1024; i += 256) sWt[i] = W2[(i & 63) * 16 + (i >> 6)];
    if (tid < 64) sb[tid] = b2[tid];
    __syncthreads();

    int w = (blockIdx.x * 256 + tid) >> 5;
    int lane = tid & 31;
    int wl = tid >> 5;
    if (w >= n) return;
    int cnt = g_cnt[w], base = w * CAP;
    int cnt4 = (cnt + 3) & ~3;
    float dv = g_dinv[w];
    int e = lane >> 3, c = lane & 7;     // lane = e*8 + c
    float2 acc = (e == 0) ? __half22float2(__ldg(&g_h1[w * 8 + c])) : make_float2(0.f, 0.f);
#pragma unroll 2
    for (int i = e; i < cnt4; i += 4) {   // cnt4 % 4 == 0: uniform trips
        int s = __ldg(&g_idx[base + i]);
        float2 v = __half22float2(__ldg(&g_h1[s * 8 + c]));
        acc.x += v.x; acc.y += v.y;
    }
#pragma unroll
    for (int o = 8; o <= 16; o <<= 1) {   // reduce over e (lane bits 3..4)
        acc.x += __shfl_xor_sync(0xffffffffu, acc.x, o);
        acc.y += __shfl_xor_sync(0xffffffffu, acc.y, o);
    }
    if (lane < 8) { stage[wl][2 * lane] = dv * acc.x; stage[wl][2 * lane + 1] = dv * acc.y; }
    __syncwarp();
    float a0 = sb[2 * lane], a1 = sb[2 * lane + 1];
    const float2* sW2 = reinterpret_cast<const float2*>(sWt);
#pragma unroll
    for (int k = 0; k < 16; k++) {
        float s = stage[wl][k];
        float2 wv = sW2[k * 32 + lane];
        a0 = fmaf(s, wv.x, a0);
        a1 = fmaf(s, wv.y, a1);
    }
    g_h2[w * 32 + lane] = __floats2half2_rn(dv * fmaxf(a0, 0.f), dv * fmaxf(a1, 0.f));
}

// ---- Layer 3: gather h2~ (warp/node, int4 idx) + 64->64 relu + project Wf -> t~ ----
__global__ void __launch_bounds__(256) k_layer3(const float* __restrict__ W3,
                                                const float* __restrict__ b3, int n) {
    __shared__ float sWt[64 * 64];    // sWt[k*64+j] = W3[j*64+k]
    __shared__ float sb[64];
    __shared__ float stage[8][64];
    int tid = threadIdx.x;
    for (int i = tid; i < 4096; i += 256) sWt[i] = W3[(i & 63) * 64 + (i >> 6)];
    if (tid < 64) sb[tid] = b3[tid];
    __syncthreads();

    int w = (blockIdx.x * 256 + tid) >> 5;
    int lane = tid & 31;
    int wl = tid >> 5;
    if (w >= n) return;
    int cnt = g_cnt[w];
    int cnt4 = (cnt + 3) & ~3;
    float dv = g_dinv[w];
    const int4* ip = reinterpret_cast<const int4*>(g_idx + w * CAP);   // 320B-aligned
    float2 acc0 = __half22float2(__ldg(&g_h2[w * 32 + lane]));         // self term
    float2 acc1 = make_float2(0.f, 0.f);
    int i = 0;
    for (; i + 8 <= cnt4; i += 8) {
        int4 a = __ldg(ip + (i >> 2));
        int4 b = __ldg(ip + (i >> 2) + 1);
        float2 v0 = __half22float2(__ldg(&g_h2[a.x * 32 + lane]));
        float2 v1 = __half22float2(__ldg(&g_h2[a.y * 32 + lane]));
        float2 v2 = __half22float2(__ldg(&g_h2[a.z * 32 + lane]));
        float2 v3 = __half22float2(__ldg(&g_h2[a.w * 32 + lane]));
        float2 v4 = __half22float2(__ldg(&g_h2[b.x * 32 + lane]));
        float2 v5 = __half22float2(__ldg(&g_h2[b.y * 32 + lane]));
        float2 v6 = __half22float2(__ldg(&g_h2[b.z * 32 + lane]));
        float2 v7 = __half22float2(__ldg(&g_h2[b.w * 32 + lane]));
        acc0.x += v0.x + v1.x + v2.x + v3.x;
        acc0.y += v0.y + v1.y + v2.y + v3.y;
        acc1.x += v4.x + v5.x + v6.x + v7.x;
        acc1.y += v4.y + v5.y + v6.y + v7.y;
    }
    if (i < cnt4) {   // exactly 4 remain
        int4 a = __ldg(ip + (i >> 2));
        float2 v0 = __half22float2(__ldg(&g_h2[a.x * 32 + lane]));
        float2 v1 = __half22float2(__ldg(&g_h2[a.y * 32 + lane]));
        float2 v2 = __half22float2(__ldg(&g_h2[a.z * 32 + lane]));
        float2 v3 = __half22float2(__ldg(&g_h2[a.w * 32 + lane]));
        acc0.x += v0.x + v1.x + v2.x + v3.x;
        acc0.y += v0.y + v1.y + v2.y + v3.y;
    }
    acc0.x += acc1.x; acc0.y += acc1.y;
    stage[wl][2 * lane] = dv * acc0.x;
    stage[wl][2 * lane + 1] = dv * acc0.y;
    __syncwarp();
    // transform 64->64 (+bias, relu)
    float a0 = sb[2 * lane], a1 = sb[2 * lane + 1];
    const float2* sW2 = reinterpret_cast<const float2*>(sWt);
#pragma unroll
    for (int k = 0; k < 64; k++) {
        float s = stage[wl][k];
        float2 wv = sW2[k * 32 + lane];
        a0 = fmaf(s, wv.x, a0);
        a1 = fmaf(s, wv.y, a1);
    }
    a0 = fmaxf(a0, 0.0f);
    a1 = fmaxf(a1, 0.0f);
    // project with fused Wf [2,64], pre-scale by dinv for the final pass
    float t0 = a0 * g_wf[2 * lane]      + a1 * g_wf[2 * lane + 1];
    float t1 = a0 * g_wf[64 + 2 * lane] + a1 * g_wf[64 + 2 * lane + 1];
#pragma unroll
    for (int o = 16; o > 0; o >>= 1) {
        t0 += __shfl_down_sync(0xffffffffu, t0, o);
        t1 += __shfl_down_sync(0xffffffffu, t1, o);
    }
    if (lane == 0) g_t[w] = make_float2(dv * t0, dv * t1);
}

// ---- final: out[v] = bf + dinv[v]*(sum t~[s] + t~[v]); 4 lanes/node; zero g_cnt ----
__global__ void __launch_bounds__(256) k_out(float* __restrict__ out, int n) {
    int t = blockIdx.x * blockDim.x + threadIdx.x;
    int v = t >> 2, l = t & 3;
    bool valid = v < n;
    int vv = valid ? v : n - 1;
    int cnt = g_cnt[vv];
    int nb = ((cnt + 3) & ~3) >> 2;
    const int4* ip = reinterpret_cast<const int4*>(g_idx + vv * CAP);
    float2 acc = make_float2(0.f, 0.f);
    for (int b = l; b < nb; b += 4) {
        int4 a = __ldg(ip + b);
        float2 v0 = __ldg(&g_t[a.x]);
        float2 v1 = __ldg(&g_t[a.y]);
        float2 v2 = __ldg(&g_t[a.z]);
        float2 v3 = __ldg(&g_t[a.w]);
        acc.x += v0.x + v1.x + v2.x + v3.x;
        acc.y += v0.y + v1.y + v2.y + v3.y;
    }
    acc.x += __shfl_xor_sync(0xffffffffu, acc.x, 1);
    acc.y += __shfl_xor_sync(0xffffffffu, acc.y, 1);
    acc.x += __shfl_xor_sync(0xffffffffu, acc.x, 2);
    acc.y += __shfl_xor_sync(0xffffffffu, acc.y, 2);
    if (valid && l == 0) {
        float2 self = g_t[v];
        float dv = g_dinv[v];
        float2 o;
        o.x = g_bf[0] + dv * (acc.x + self.x);
        o.y = g_bf[1] + dv * (acc.y + self.y);
        reinterpret_cast<float2*>(out)[v] = o;
        g_cnt[v] = 0;   // restore invariant for the next replay
    }
}

extern "C" void kernel_launch(void* const* d_in, const int* in_sizes, int n_in,
                              void* d_out, int out_size) {
    const float* x  = (const float*)d_in[0];
    const int*   ei = (const int*)d_in[1];
    const float* W1 = (const float*)d_in[2];
    const float* b1 = (const float*)d_in[3];
    const float* W2 = (const float*)d_in[4];
    const float* b2 = (const float*)d_in[5];
    const float* W3 = (const float*)d_in[6];
    const float* b3 = (const float*)d_in[7];
    const float* W4 = (const float*)d_in[8];
    const float* b4 = (const float*)d_in[9];
    const float* Wl = (const float*)d_in[10];
    const float* bl = (const float*)d_in[11];
    float* out = (float*)d_out;

    int n = in_sizes[0] / 8;   // 100000
    int E = in_sizes[1] / 2;   // 3200000
    const int* src = ei;       // edge_index[0]
    const int* dst = ei + E;   // edge_index[1]
    int E4 = E / 4;

    const int B = 256;
    auto blocks = [&](long total) { return (int)((total + B - 1) / B); };

    k_build<<<blocks(E4), B>>>(src, dst, E4, E);
    k_node<<<blocks(n), B>>>(x, W4, b4, Wl, bl, n);
    k_layer1<<<blocks((long)n * 32), B>>>(W1, b1, n);
    k_layer2<<<blocks((long)n * 32), B>>>(W2, b2, n);
    k_layer3<<<blocks((long)n * 32), B>>>(W3, b3, n);
    k_out<<<blocks((long)n * 4), B>>>(out, n);
}

// round 11
// speedup vs baseline: 3.1481x; 1.5631x over previous
#include <cuda_runtime.h>
#include <cuda_fp16.h>

// Problem constants (fixed by the dataset)
#define NN 100000
#define EE 3200000
#define CAP 80          // fixed CSR row capacity (max degree ~59 for this dataset; guarded)

// Scratch (device globals; no allocation allowed). Zero-initialized at load.
// g_cnt starts zero and is re-zeroed by k_out at the end of every launch, so
// every call performs identical work on identical state (deterministic).
// Feature arrays have one extra zero row (index NN) targeted by pad slots.
__device__ int   g_cnt[NN];                             // per-dst in-degree
__device__ float g_dinv[NN];                            // 1/sqrt(deg+1)
__device__ int   g_idx[NN * CAP];                       // bucketed src indices
__device__ __align__(16) __half2 g_xs[(NN + 1) * 4];    // x~ = dinv*x, fp16
__device__ __align__(16) __half2 g_h1[(NN + 1) * 8];    // h1~ = dinv*h1, fp16
__device__ __align__(16) __half2 g_h2[(NN + 1) * 32];   // h2~ = dinv*h2, fp16
__device__ __align__(16) float2  g_t[NN + 1];           // t~ = dinv*t
__device__ float g_wf[2 * 64];                          // fused Wl@W4
__device__ float g_bf[2];                               // fused Wl@b4 + bl

// ---- build: count + place in ONE pass (g_cnt all-zero on entry) ----
__global__ void k_build(const int* __restrict__ src, const int* __restrict__ dst,
                        int E4, int E) {
    int i = blockIdx.x * blockDim.x + threadIdx.x;
    if (i == 0) {   // tail (E not divisible by 4) — no-op for E=3.2M
        for (int e = E4 * 4; e < E; e++) {
            int p = atomicAdd(&g_cnt[dst[e]], 1);
            if (p < CAP) g_idx[dst[e] * CAP + p] = src[e];
        }
    }
    if (i >= E4) return;
    int4 s = __ldg(reinterpret_cast<const int4*>(src) + i);
    int4 d = __ldg(reinterpret_cast<const int4*>(dst) + i);
    int p;
    p = atomicAdd(&g_cnt[d.x], 1); if (p < CAP) g_idx[d.x * CAP + p] = s.x;
    p = atomicAdd(&g_cnt[d.y], 1); if (p < CAP) g_idx[d.y * CAP + p] = s.y;
    p = atomicAdd(&g_cnt[d.z], 1); if (p < CAP) g_idx[d.z * CAP + p] = s.z;
    p = atomicAdd(&g_cnt[d.w], 1); if (p < CAP) g_idx[d.w * CAP + p] = s.w;
}

// ---- per-node: dinv + pad slots + x~ conversion; block 0 also builds Wf/bf ----
__global__ void k_node(const float* __restrict__ x,
                       const float* __restrict__ W4, const float* __restrict__ b4,
                       const float* __restrict__ Wl, const float* __restrict__ bl, int n) {
    if (blockIdx.x == 0 && threadIdx.x < 128) {
        int k = threadIdx.x & 63, j = threadIdx.x >> 6;
        float a = 0.0f;
#pragma unroll
        for (int m = 0; m < 10; m++) a += Wl[j * 10 + m] * W4[m * 64 + k];
        g_wf[j * 64 + k] = a;
        if (k == 0) {
            float bb = bl[j];
#pragma unroll
            for (int m = 0; m < 10; m++) bb += Wl[j * 10 + m] * b4[m];
            g_bf[j] = bb;
        }
    }
    int v = blockIdx.x * blockDim.x + threadIdx.x;
    if (v >= n) return;
    int cnt = g_cnt[v];
    if (cnt > CAP) { cnt = CAP; g_cnt[v] = CAP; }   // safety (never for this dataset)
    float dv = rsqrtf((float)(cnt + 1));            // +1: self loop
    g_dinv[v] = dv;
    int cnt4 = (cnt + 3) & ~3;
    if (cnt4 > CAP) cnt4 = CAP;
    for (int j = cnt; j < cnt4; j++) g_idx[v * CAP + j] = n;   // pads -> zero row
    float4 a = __ldg(reinterpret_cast<const float4*>(x) + v * 2);
    float4 b = __ldg(reinterpret_cast<const float4*>(x) + v * 2 + 1);
    g_xs[v * 4 + 0] = __floats2half2_rn(dv * a.x, dv * a.y);
    g_xs[v * 4 + 1] = __floats2half2_rn(dv * a.z, dv * a.w);
    g_xs[v * 4 + 2] = __floats2half2_rn(dv * b.x, dv * b.y);
    g_xs[v * 4 + 3] = __floats2half2_rn(dv * b.z, dv * b.w);
}

// ---- Layer 1: gather x~ (8 edges x 4 chunks per warp) + 8->16 relu -> h1~ fp16 ----
__global__ void __launch_bounds__(256) k_layer1(const float* __restrict__ W1,
                                                const float* __restrict__ b1, int n) {
    __shared__ float sWt[8 * 16];     // k-major: sWt[k*16+j] = W1[j*8+k]
    __shared__ float sb[16];
    __shared__ float stage[8][8];
    int tid = threadIdx.x;
    if (tid < 128) sWt[tid] = W1[(tid & 15) * 8 + (tid >> 4)];
    if (tid < 16) sb[tid] = b1[tid];
    __syncthreads();

    int w = (blockIdx.x * 256 + tid) >> 5;
    int lane = tid & 31;
    int wl = tid >> 5;
    if (w >= n) return;
    int cnt = g_cnt[w], base = w * CAP;
    int cnt4 = (cnt + 3) & ~3;
    float dv = g_dinv[w];
    int e = lane >> 2, c = lane & 3;     // lane = e*4 + c
    float2 acc = (e == 0) ? __half22float2(__ldg(&g_xs[w * 4 + c])) : make_float2(0.f, 0.f);
#pragma unroll 2
    for (int i = e; i < cnt4; i += 8) {
        int s = __ldg(&g_idx[base + i]);
        float2 v = __half22float2(__ldg(&g_xs[s * 4 + c]));
        acc.x += v.x; acc.y += v.y;
    }
#pragma unroll
    for (int o = 4; o <= 16; o <<= 1) {   // reduce over e (lane bits 2..4)
        acc.x += __shfl_xor_sync(0xffffffffu, acc.x, o);
        acc.y += __shfl_xor_sync(0xffffffffu, acc.y, o);
    }
    if (lane < 4) { stage[wl][2 * lane] = dv * acc.x; stage[wl][2 * lane + 1] = dv * acc.y; }
    __syncwarp();
    if (lane < 8) {
        const float2* sW2 = reinterpret_cast<const float2*>(sWt);
        float a0 = sb[2 * lane], a1 = sb[2 * lane + 1];
#pragma unroll
        for (int k = 0; k < 8; k++) {
            float s = stage[wl][k];
            float2 wv = sW2[k * 8 + lane];
            a0 = fmaf(s, wv.x, a0);
            a1 = fmaf(s, wv.y, a1);
        }
        g_h1[w * 8 + lane] = __floats2half2_rn(dv * fmaxf(a0, 0.f), dv * fmaxf(a1, 0.f));
    }
}

// ---- Layer 2: gather h1~ (4 edges x 8 chunks per warp) + 16->64 relu -> h2~ ----
__global__ void __launch_bounds__(256) k_layer2(const float* __restrict__ W2,
                                                const float* __restrict__ b2, int n) {
    __shared__ float sWt[16 * 64];    // sWt[k*64+j] = W2[j*16+k]
    __shared__ float sb[64];
    __shared__ float stage[8][16];
    int tid = threadIdx.x;
    for (int i = tid; i < 1024; i += 256) sWt[i] = W2[(i & 63) * 16 + (i >> 6)];
    if (tid < 64) sb[tid] = b2[tid];
    __syncthreads();

    int w = (blockIdx.x * 256 + tid) >> 5;
    int lane = tid & 31;
    int wl = tid >> 5;
    if (w >= n) return;
    int cnt = g_cnt[w], base = w * CAP;
    int cnt4 = (cnt + 3) & ~3;
    float dv = g_dinv[w];
    int e = lane >> 3, c = lane & 7;     // lane = e*8 + c
    float2 acc = (e == 0) ? __half22float2(__ldg(&g_h1[w * 8 + c])) : make_float2(0.f, 0.f);
#pragma unroll 2
    for (int i = e; i < cnt4; i += 4) {   // cnt4 % 4 == 0: uniform trips
        int s = __ldg(&g_idx[base + i]);
        float2 v = __half22float2(__ldg(&g_h1[s * 8 + c]));
        acc.x += v.x; acc.y += v.y;
    }
#pragma unroll
    for (int o = 8; o <= 16; o <<= 1) {   // reduce over e (lane bits 3..4)
        acc.x += __shfl_xor_sync(0xffffffffu, acc.x, o);
        acc.y += __shfl_xor_sync(0xffffffffu, acc.y, o);
    }
    if (lane < 8) { stage[wl][2 * lane] = dv * acc.x; stage[wl][2 * lane + 1] = dv * acc.y; }
    __syncwarp();
    float a0 = sb[2 * lane], a1 = sb[2 * lane + 1];
    const float2* sW2 = reinterpret_cast<const float2*>(sWt);
#pragma unroll
    for (int k = 0; k < 16; k++) {
        float s = stage[wl][k];
        float2 wv = sW2[k * 32 + lane];
        a0 = fmaf(s, wv.x, a0);
        a1 = fmaf(s, wv.y, a1);
    }
    g_h2[w * 32 + lane] = __floats2half2_rn(dv * fmaxf(a0, 0.f), dv * fmaxf(a1, 0.f));
}

// ---- Layer 3 (block-cooperative): 32 nodes/block.
// Phase 1: each warp gathers 4 nodes -> stage[32][33] half2 (conflict-free pad).
// Phase 2: warp wl computes j-slice [8wl,8wl+8) for ALL 32 nodes (lane = node),
//          weights read once per warp via broadcast LDS.128 (32x less smem traffic).
// Then bias+relu+Wf projection; per-slice partials reduced across warps -> g_t. ----
__global__ void __launch_bounds__(256) k_layer3(const float* __restrict__ W3,
                                                const float* __restrict__ b3, int n) {
    __shared__ float sWt[64 * 64];        // sWt[k*64+j] = W3[j*64+k]
    __shared__ float sb[64];
    __shared__ float swf[128];
    __shared__ __half2 stage[32][33];     // row stride 33*4B: bank(m,k)=(m+k/2)%32 distinct
    __shared__ float tpart[8][32][2];     // per-jslice partial projections
    int tid = threadIdx.x;
    for (int i = tid; i < 4096; i += 256) sWt[i] = W3[(i & 63) * 64 + (i >> 6)];
    if (tid < 64) sb[tid] = b3[tid];
    if (tid >= 64 && tid < 192) swf[tid - 64] = g_wf[tid - 64];
    __syncthreads();

    int lane = tid & 31;
    int wl = tid >> 5;
    int nodebase = blockIdx.x * 32;

    // ---- Phase 1: gather (warp wl -> nodes nodebase + 4*wl .. +3) ----
    for (int q = 0; q < 4; q++) {
        int m = wl * 4 + q;
        int w = nodebase + m;
        float2 acc0 = make_float2(0.f, 0.f), acc1 = make_float2(0.f, 0.f);
        float dv = 0.0f;
        if (w < n) {
            int cnt = g_cnt[w];
            int cnt4 = (cnt + 3) & ~3;
            dv = g_dinv[w];
            const int4* ip = reinterpret_cast<const int4*>(g_idx + w * CAP);
            acc0 = __half22float2(__ldg(&g_h2[w * 32 + lane]));   // self term
            int i = 0;
            for (; i + 8 <= cnt4; i += 8) {
                int4 a = __ldg(ip + (i >> 2));
                int4 b = __ldg(ip + (i >> 2) + 1);
                float2 v0 = __half22float2(__ldg(&g_h2[a.x * 32 + lane]));
                float2 v1 = __half22float2(__ldg(&g_h2[a.y * 32 + lane]));
                float2 v2 = __half22float2(__ldg(&g_h2[a.z * 32 + lane]));
                float2 v3 = __half22float2(__ldg(&g_h2[a.w * 32 + lane]));
                float2 v4 = __half22float2(__ldg(&g_h2[b.x * 32 + lane]));
                float2 v5 = __half22float2(__ldg(&g_h2[b.y * 32 + lane]));
                float2 v6 = __half22float2(__ldg(&g_h2[b.z * 32 + lane]));
                float2 v7 = __half22float2(__ldg(&g_h2[b.w * 32 + lane]));
                acc0.x += v0.x + v1.x + v2.x + v3.x;
                acc0.y += v0.y + v1.y + v2.y + v3.y;
                acc1.x += v4.x + v5.x + v6.x + v7.x;
                acc1.y += v4.y + v5.y + v6.y + v7.y;
            }
            if (i < cnt4) {   // exactly 4 remain
                int4 a = __ldg(ip + (i >> 2));
                float2 v0 = __half22float2(__ldg(&g_h2[a.x * 32 + lane]));
                float2 v1 = __half22float2(__ldg(&g_h2[a.y * 32 + lane]));
                float2 v2 = __half22float2(__ldg(&g_h2[a.z * 32 + lane]));
                float2 v3 = __half22float2(__ldg(&g_h2[a.w * 32 + lane]));
                acc0.x += v0.x + v1.x + v2.x + v3.x;
                acc0.y += v0.y + v1.y + v2.y + v3.y;
            }
        }
        stage[m][lane] = __floats2half2_rn(dv * (acc0.x + acc1.x), dv * (acc0.y + acc1.y));
    }
    __syncthreads();

    // ---- Phase 2: transform. lane = node m, warp wl = j-slice ----
    {
        int m = lane;
        int j0 = wl * 8;
        const __half* srow = reinterpret_cast<const __half*>(&stage[m][0]);
        float acc[8];
#pragma unroll
        for (int j = 0; j < 8; j++) acc[j] = sb[j0 + j];
#pragma unroll 4
        for (int k = 0; k < 64; k++) {
            float s = __half2float(srow[k]);                       // conflict-free LDS.16
            float4 w0 = *reinterpret_cast<const float4*>(&sWt[k * 64 + j0]);       // broadcast
            float4 w1 = *reinterpret_cast<const float4*>(&sWt[k * 64 + j0 + 4]);   // broadcast
            acc[0] = fmaf(s, w0.x, acc[0]);
            acc[1] = fmaf(s, w0.y, acc[1]);
            acc[2] = fmaf(s, w0.z, acc[2]);
            acc[3] = fmaf(s, w0.w, acc[3]);
            acc[4] = fmaf(s, w1.x, acc[4]);
            acc[5] = fmaf(s, w1.y, acc[5]);
            acc[6] = fmaf(s, w1.z, acc[6]);
            acc[7] = fmaf(s, w1.w, acc[7]);
        }
        float t0 = 0.f, t1 = 0.f;
#pragma unroll
        for (int j = 0; j < 8; j++) {
            float a = fmaxf(acc[j], 0.f);
            t0 = fmaf(a, swf[j0 + j], t0);
            t1 = fmaf(a, swf[64 + j0 + j], t1);
        }
        tpart[wl][m][0] = t0;
        tpart[wl][m][1] = t1;
    }
    __syncthreads();

    // ---- reduce 8 j-slice partials per node; write g_t ----
    if (wl == 0) {
        int w = nodebase + lane;
        if (w < n) {
            float s0 = 0.f, s1 = 0.f;
#pragma unroll
            for (int p = 0; p < 8; p++) { s0 += tpart[p][lane][0]; s1 += tpart[p][lane][1]; }
            float dv = g_dinv[w];
            g_t[w] = make_float2(dv * s0, dv * s1);
        }
    }
}

// ---- final: out[v] = bf + dinv[v]*(sum t~[s] + t~[v]); 4 lanes/node; zero g_cnt ----
__global__ void __launch_bounds__(256) k_out(float* __restrict__ out, int n) {
    int t = blockIdx.x * blockDim.x + threadIdx.x;
    int v = t >> 2, l = t & 3;
    bool valid = v < n;
    int vv = valid ? v : n - 1;
    int cnt = g_cnt[vv];
    int nb = ((cnt + 3) & ~3) >> 2;
    const int4* ip = reinterpret_cast<const int4*>(g_idx + vv * CAP);
    float2 acc = make_float2(0.f, 0.f);
    for (int b = l; b < nb; b += 4) {
        int4 a = __ldg(ip + b);
        float2 v0 = __ldg(&g_t[a.x]);
        float2 v1 = __ldg(&g_t[a.y]);
        float2 v2 = __ldg(&g_t[a.z]);
        float2 v3 = __ldg(&g_t[a.w]);
        acc.x += v0.x + v1.x + v2.x + v3.x;
        acc.y += v0.y + v1.y + v2.y + v3.y;
    }
    acc.x += __shfl_xor_sync(0xffffffffu, acc.x, 1);
    acc.y += __shfl_xor_sync(0xffffffffu, acc.y, 1);
    acc.x += __shfl_xor_sync(0xffffffffu, acc.x, 2);
    acc.y += __shfl_xor_sync(0xffffffffu, acc.y, 2);
    if (valid && l == 0) {
        float2 self = g_t[v];
        float dv = g_dinv[v];
        float2 o;
        o.x = g_bf[0] + dv * (acc.x + self.x);
        o.y = g_bf[1] + dv * (acc.y + self.y);
        reinterpret_cast<float2*>(out)[v] = o;
        g_cnt[v] = 0;   // restore invariant for the next replay
    }
}

extern "C" void kernel_launch(void* const* d_in, const int* in_sizes, int n_in,
                              void* d_out, int out_size) {
    const float* x  = (const float*)d_in[0];
    const int*   ei = (const int*)d_in[1];
    const float* W1 = (const float*)d_in[2];
    const float* b1 = (const float*)d_in[3];
    const float* W2 = (const float*)d_in[4];
    const float* b2 = (const float*)d_in[5];
    const float* W3 = (const float*)d_in[6];
    const float* b3 = (const float*)d_in[7];
    const float* W4 = (const float*)d_in[8];
    const float* b4 = (const float*)d_in[9];
    const float* Wl = (const float*)d_in[10];
    const float* bl = (const float*)d_in[11];
    float* out = (float*)d_out;

    int n = in_sizes[0] / 8;   // 100000
    int E = in_sizes[1] / 2;   // 3200000
    const int* src = ei;       // edge_index[0]
    const int* dst = ei + E;   // edge_index[1]
    int E4 = E / 4;

    const int B = 256;
    auto blocks = [&](long total) { return (int)((total + B - 1) / B); };

    k_build<<<blocks(E4), B>>>(src, dst, E4, E);
    k_node<<<blocks(n), B>>>(x, W4, b4, Wl, bl, n);
    k_layer1<<<blocks((long)n * 32), B>>>(W1, b1, n);
    k_layer2<<<blocks((long)n * 32), B>>>(W2, b2, n);
    k_layer3<<<(n + 31) / 32, B>>>(W3, b3, n);
    k_out<<<blocks((long)n * 4), B>>>(out, n);
}

// round 12
// speedup vs baseline: 3.3718x; 1.0710x over previous
#include <cuda_runtime.h>
#include <cuda_fp16.h>

// Problem constants (fixed by the dataset)
#define NN 100000
#define EE 3200000
#define CAP 80          // fixed CSR row capacity (max degree ~59 for this dataset; guarded)

// Scratch (device globals; no allocation allowed). Zero-initialized at load.
// g_cnt starts zero and is re-zeroed by k_out at the end of every launch, so
// every call performs identical work on identical state (deterministic).
// Feature arrays have one extra zero row (index NN) targeted by pad slots.
__device__ int   g_cnt[NN];                             // per-dst in-degree
__device__ float g_dinv[NN];                            // 1/sqrt(deg+1)
__device__ int   g_idx[NN * CAP];                       // bucketed src indices
__device__ __align__(16) __half2 g_xs[(NN + 1) * 4];    // x~ = dinv*x, fp16
__device__ __align__(16) __half2 g_h1[(NN + 1) * 8];    // h1~ = dinv*h1, fp16
__device__ __align__(16) __half2 g_h2[(NN + 1) * 32];   // h2~ = dinv*h2, fp16
__device__ __align__(16) float2  g_t[NN + 1];           // t~ = dinv*t
__device__ float g_wf[2 * 64];                          // fused Wl@W4
__device__ float g_bf[2];                               // fused Wl@b4 + bl

// ---- build: count + place in ONE pass (g_cnt all-zero on entry) ----
__global__ void k_build(const int* __restrict__ src, const int* __restrict__ dst,
                        int E4, int E) {
    int i = blockIdx.x * blockDim.x + threadIdx.x;
    if (i == 0) {   // tail (E not divisible by 4) — no-op for E=3.2M
        for (int e = E4 * 4; e < E; e++) {
            int p = atomicAdd(&g_cnt[dst[e]], 1);
            if (p < CAP) g_idx[dst[e] * CAP + p] = src[e];
        }
    }
    if (i >= E4) return;
    int4 s = __ldg(reinterpret_cast<const int4*>(src) + i);
    int4 d = __ldg(reinterpret_cast<const int4*>(dst) + i);
    int p;
    p = atomicAdd(&g_cnt[d.x], 1); if (p < CAP) g_idx[d.x * CAP + p] = s.x;
    p = atomicAdd(&g_cnt[d.y], 1); if (p < CAP) g_idx[d.y * CAP + p] = s.y;
    p = atomicAdd(&g_cnt[d.z], 1); if (p < CAP) g_idx[d.z * CAP + p] = s.z;
    p = atomicAdd(&g_cnt[d.w], 1); if (p < CAP) g_idx[d.w * CAP + p] = s.w;
}

// ---- per-node: dinv + pad slots + x~ conversion; block 0 also builds Wf/bf ----
__global__ void k_node(const float* __restrict__ x,
                       const float* __restrict__ W4, const float* __restrict__ b4,
                       const float* __restrict__ Wl, const float* __restrict__ bl, int n) {
    if (blockIdx.x == 0 && threadIdx.x < 128) {
        int k = threadIdx.x & 63, j = threadIdx.x >> 6;
        float a = 0.0f;
#pragma unroll
        for (int m = 0; m < 10; m++) a += Wl[j * 10 + m] * W4[m * 64 + k];
        g_wf[j * 64 + k] = a;
        if (k == 0) {
            float bb = bl[j];
#pragma unroll
            for (int m = 0; m < 10; m++) bb += Wl[j * 10 + m] * b4[m];
            g_bf[j] = bb;
        }
    }
    int v = blockIdx.x * blockDim.x + threadIdx.x;
    if (v >= n) return;
    int cnt = g_cnt[v];
    if (cnt > CAP) { cnt = CAP; g_cnt[v] = CAP; }   // safety (never for this dataset)
    float dv = rsqrtf((float)(cnt + 1));            // +1: self loop
    g_dinv[v] = dv;
    int cnt4 = (cnt + 3) & ~3;
    if (cnt4 > CAP) cnt4 = CAP;
    for (int j = cnt; j < cnt4; j++) g_idx[v * CAP + j] = n;   // pads -> zero row
    float4 a = __ldg(reinterpret_cast<const float4*>(x) + v * 2);
    float4 b = __ldg(reinterpret_cast<const float4*>(x) + v * 2 + 1);
    g_xs[v * 4 + 0] = __floats2half2_rn(dv * a.x, dv * a.y);
    g_xs[v * 4 + 1] = __floats2half2_rn(dv * a.z, dv * a.w);
    g_xs[v * 4 + 2] = __floats2half2_rn(dv * b.x, dv * b.y);
    g_xs[v * 4 + 3] = __floats2half2_rn(dv * b.z, dv * b.w);
}

// ---- Layer 1: gather x~ (8 edges x 4 chunks per warp) + 8->16 relu -> h1~ fp16 ----
__global__ void __launch_bounds__(256) k_layer1(const float* __restrict__ W1,
                                                const float* __restrict__ b1, int n) {
    __shared__ float sWt[8 * 16];     // k-major: sWt[k*16+j] = W1[j*8+k]
    __shared__ float sb[16];
    __shared__ float stage[8][8];
    int tid = threadIdx.x;
    if (tid < 128) sWt[tid] = W1[(tid & 15) * 8 + (tid >> 4)];
    if (tid < 16) sb[tid] = b1[tid];
    __syncthreads();

    int w = (blockIdx.x * 256 + tid) >> 5;
    int lane = tid & 31;
    int wl = tid >> 5;
    if (w >= n) return;
    int cnt = g_cnt[w], base = w * CAP;
    int cnt4 = (cnt + 3) & ~3;
    float dv = g_dinv[w];
    int e = lane >> 2, c = lane & 3;     // lane = e*4 + c
    float2 acc = (e == 0) ? __half22float2(__ldg(&g_xs[w * 4 + c])) : make_float2(0.f, 0.f);
#pragma unroll 2
    for (int i = e; i < cnt4; i += 8) {
        int s = __ldg(&g_idx[base + i]);
        float2 v = __half22float2(__ldg(&g_xs[s * 4 + c]));
        acc.x += v.x; acc.y += v.y;
    }
#pragma unroll
    for (int o = 4; o <= 16; o <<= 1) {   // reduce over e (lane bits 2..4)
        acc.x += __shfl_xor_sync(0xffffffffu, acc.x, o);
        acc.y += __shfl_xor_sync(0xffffffffu, acc.y, o);
    }
    if (lane < 4) { stage[wl][2 * lane] = dv * acc.x; stage[wl][2 * lane + 1] = dv * acc.y; }
    __syncwarp();
    if (lane < 8) {
        const float2* sW2 = reinterpret_cast<const float2*>(sWt);
        float a0 = sb[2 * lane], a1 = sb[2 * lane + 1];
#pragma unroll
        for (int k = 0; k < 8; k++) {
            float s = stage[wl][k];
            float2 wv = sW2[k * 8 + lane];
            a0 = fmaf(s, wv.x, a0);
            a1 = fmaf(s, wv.y, a1);
        }
        g_h1[w * 8 + lane] = __floats2half2_rn(dv * fmaxf(a0, 0.f), dv * fmaxf(a1, 0.f));
    }
}

// ---- Layer 2 (block-cooperative): 32 nodes/block.
// Phase 1: each warp gathers 4 nodes (4 edges x 8 chunks) -> stage[32][17] float.
// Phase 2: warp wl computes j-slice [8wl,8wl+8) for ALL 32 nodes (lane = node),
//          weights read via broadcast LDS.128 (32x less weight smem traffic).
// Phase 3: outputs staged in smem, written coalesced to g_h2. ----
__global__ void __launch_bounds__(256) k_layer2(const float* __restrict__ W2,
                                                const float* __restrict__ b2, int n) {
    __shared__ float sWt[16 * 64];        // sWt[k*64+j] = W2[j*16+k]
    __shared__ float sb[64];
    __shared__ float stage[32][17];       // [node][k]; 17m+k mod 32 distinct -> conflict-free
    __shared__ __half2 sout[32][33];      // [node][j2]; 33m+j2 mod 32 distinct
    int tid = threadIdx.x;
    for (int i = tid; i < 1024; i += 256) sWt[i] = W2[(i & 63) * 16 + (i >> 6)];
    if (tid < 64) sb[tid] = b2[tid];
    __syncthreads();

    int lane = tid & 31;
    int wl = tid >> 5;
    int nodebase = blockIdx.x * 32;

    // ---- Phase 1: gather (warp wl -> nodes nodebase + 4*wl + q) ----
    int e = lane >> 3, c = lane & 7;      // lane = e*8 + c
    for (int q = 0; q < 4; q++) {
        int m = wl * 4 + q;
        int w = nodebase + m;
        float2 acc = make_float2(0.f, 0.f);
        float dv = 0.f;
        if (w < n) {
            int cnt = g_cnt[w], base = w * CAP;
            int cnt4 = (cnt + 3) & ~3;
            dv = g_dinv[w];
            if (e == 0) acc = __half22float2(__ldg(&g_h1[w * 8 + c]));   // self term
#pragma unroll 2
            for (int i = e; i < cnt4; i += 4) {
                int s = __ldg(&g_idx[base + i]);
                float2 v = __half22float2(__ldg(&g_h1[s * 8 + c]));
                acc.x += v.x; acc.y += v.y;
            }
        }
        acc.x += __shfl_xor_sync(0xffffffffu, acc.x, 8);
        acc.y += __shfl_xor_sync(0xffffffffu, acc.y, 8);
        acc.x += __shfl_xor_sync(0xffffffffu, acc.x, 16);
        acc.y += __shfl_xor_sync(0xffffffffu, acc.y, 16);
        if (lane < 8) {
            stage[m][2 * lane] = dv * acc.x;
            stage[m][2 * lane + 1] = dv * acc.y;
        }
    }
    __syncthreads();

    // ---- Phase 2: transform 16->64. lane = node m, warp wl = j-slice ----
    {
        int m = lane;
        int j0 = wl * 8;
        int w = nodebase + m;
        float dv = (w < n) ? g_dinv[w] : 0.f;
        float acc[8];
#pragma unroll
        for (int j = 0; j < 8; j++) acc[j] = sb[j0 + j];
#pragma unroll
        for (int k = 0; k < 16; k++) {
            float s = stage[m][k];                                       // conflict-free
            float4 w0 = *reinterpret_cast<const float4*>(&sWt[k * 64 + j0]);       // broadcast
            float4 w1 = *reinterpret_cast<const float4*>(&sWt[k * 64 + j0 + 4]);   // broadcast
            acc[0] = fmaf(s, w0.x, acc[0]);
            acc[1] = fmaf(s, w0.y, acc[1]);
            acc[2] = fmaf(s, w0.z, acc[2]);
            acc[3] = fmaf(s, w0.w, acc[3]);
            acc[4] = fmaf(s, w1.x, acc[4]);
            acc[5] = fmaf(s, w1.y, acc[5]);
            acc[6] = fmaf(s, w1.z, acc[6]);
            acc[7] = fmaf(s, w1.w, acc[7]);
        }
#pragma unroll
        for (int r = 0; r < 4; r++) {
            sout[m][wl * 4 + r] = __floats2half2_rn(dv * fmaxf(acc[2 * r], 0.f),
                                                    dv * fmaxf(acc[2 * r + 1], 0.f));
        }
    }
    __syncthreads();

    // ---- Phase 3: coalesced write (warp wl -> nodes 4wl..4wl+3) ----
    for (int q = 0; q < 4; q++) {
        int m = wl * 4 + q;
        int w = nodebase + m;
        if (w < n) g_h2[w * 32 + lane] = sout[m][lane];
    }
}

// ---- Layer 3 (block-cooperative): 32 nodes/block.
// Phase 1: each warp gathers 4 nodes -> stage[32][33] half2 (conflict-free pad).
// Phase 2: warp wl computes j-slice [8wl,8wl+8) for ALL 32 nodes (lane = node),
//          weights read once per warp via broadcast LDS.128 (32x less smem traffic).
// Then bias+relu+Wf projection; per-slice partials reduced across warps -> g_t. ----
__global__ void __launch_bounds__(256) k_layer3(const float* __restrict__ W3,
                                                const float* __restrict__ b3, int n) {
    __shared__ float sWt[64 * 64];        // sWt[k*64+j] = W3[j*64+k]
    __shared__ float sb[64];
    __shared__ float swf[128];
    __shared__ __half2 stage[32][33];     // row stride 33*4B: bank(m,k)=(m+k/2)%32 distinct
    __shared__ float tpart[8][32][2];     // per-jslice partial projections
    int tid = threadIdx.x;
    for (int i = tid; i < 4096; i += 256) sWt[i] = W3[(i & 63) * 64 + (i >> 6)];
    if (tid < 64) sb[tid] = b3[tid];
    if (tid >= 64 && tid < 192) swf[tid - 64] = g_wf[tid - 64];
    __syncthreads();

    int lane = tid & 31;
    int wl = tid >> 5;
    int nodebase = blockIdx.x * 32;

    // ---- Phase 1: gather (warp wl -> nodes nodebase + 4*wl .. +3) ----
    for (int q = 0; q < 4; q++) {
        int m = wl * 4 + q;
        int w = nodebase + m;
        float2 acc0 = make_float2(0.f, 0.f), acc1 = make_float2(0.f, 0.f);
        float dv = 0.0f;
        if (w < n) {
            int cnt = g_cnt[w];
            int cnt4 = (cnt + 3) & ~3;
            dv = g_dinv[w];
            const int4* ip = reinterpret_cast<const int4*>(g_idx + w * CAP);
            acc0 = __half22float2(__ldg(&g_h2[w * 32 + lane]));   // self term
            int i = 0;
            for (; i + 8 <= cnt4; i += 8) {
                int4 a = __ldg(ip + (i >> 2));
                int4 b = __ldg(ip + (i >> 2) + 1);
                float2 v0 = __half22float2(__ldg(&g_h2[a.x * 32 + lane]));
                float2 v1 = __half22float2(__ldg(&g_h2[a.y * 32 + lane]));
                float2 v2 = __half22float2(__ldg(&g_h2[a.z * 32 + lane]));
                float2 v3 = __half22float2(__ldg(&g_h2[a.w * 32 + lane]));
                float2 v4 = __half22float2(__ldg(&g_h2[b.x * 32 + lane]));
                float2 v5 = __half22float2(__ldg(&g_h2[b.y * 32 + lane]));
                float2 v6 = __half22float2(__ldg(&g_h2[b.z * 32 + lane]));
                float2 v7 = __half22float2(__ldg(&g_h2[b.w * 32 + lane]));
                acc0.x += v0.x + v1.x + v2.x + v3.x;
                acc0.y += v0.y + v1.y + v2.y + v3.y;
                acc1.x += v4.x + v5.x + v6.x + v7.x;
                acc1.y += v4.y + v5.y + v6.y + v7.y;
            }
            if (i < cnt4) {   // exactly 4 remain
                int4 a = __ldg(ip + (i >> 2));
                float2 v0 = __half22float2(__ldg(&g_h2[a.x * 32 + lane]));
                float2 v1 = __half22float2(__ldg(&g_h2[a.y * 32 + lane]));
                float2 v2 = __half22float2(__ldg(&g_h2[a.z * 32 + lane]));
                float2 v3 = __half22float2(__ldg(&g_h2[a.w * 32 + lane]));
                acc0.x += v0.x + v1.x + v2.x + v3.x;
                acc0.y += v0.y + v1.y + v2.y + v3.y;
            }
        }
        stage[m][lane] = __floats2half2_rn(dv * (acc0.x + acc1.x), dv * (acc0.y + acc1.y));
    }
    __syncthreads();

    // ---- Phase 2: transform. lane = node m, warp wl = j-slice ----
    {
        int m = lane;
        int j0 = wl * 8;
        const __half* srow = reinterpret_cast<const __half*>(&stage[m][0]);
        float acc[8];
#pragma unroll
        for (int j = 0; j < 8; j++) acc[j] = sb[j0 + j];
#pragma unroll 4
        for (int k = 0; k < 64; k++) {
            float s = __half2float(srow[k]);                       // conflict-free LDS.16
            float4 w0 = *reinterpret_cast<const float4*>(&sWt[k * 64 + j0]);       // broadcast
            float4 w1 = *reinterpret_cast<const float4*>(&sWt[k * 64 + j0 + 4]);   // broadcast
            acc[0] = fmaf(s, w0.x, acc[0]);
            acc[1] = fmaf(s, w0.y, acc[1]);
            acc[2] = fmaf(s, w0.z, acc[2]);
            acc[3] = fmaf(s, w0.w, acc[3]);
            acc[4] = fmaf(s, w1.x, acc[4]);
            acc[5] = fmaf(s, w1.y, acc[5]);
            acc[6] = fmaf(s, w1.z, acc[6]);
            acc[7] = fmaf(s, w1.w, acc[7]);
        }
        float t0 = 0.f, t1 = 0.f;
#pragma unroll
        for (int j = 0; j < 8; j++) {
            float a = fmaxf(acc[j], 0.f);
            t0 = fmaf(a, swf[j0 + j], t0);
            t1 = fmaf(a, swf[64 + j0 + j], t1);
        }
        tpart[wl][m][0] = t0;
        tpart[wl][m][1] = t1;
    }
    __syncthreads();

    // ---- reduce 8 j-slice partials per node; write g_t ----
    if (wl == 0) {
        int w = nodebase + lane;
        if (w < n) {
            float s0 = 0.f, s1 = 0.f;
#pragma unroll
            for (int p = 0; p < 8; p++) { s0 += tpart[p][lane][0]; s1 += tpart[p][lane][1]; }
            float dv = g_dinv[w];
            g_t[w] = make_float2(dv * s0, dv * s1);
        }
    }
}

// ---- final: out[v] = bf + dinv[v]*(sum t~[s] + t~[v]); 4 lanes/node; zero g_cnt ----
__global__ void __launch_bounds__(256) k_out(float* __restrict__ out, int n) {
    int t = blockIdx.x * blockDim.x + threadIdx.x;
    int v = t >> 2, l = t & 3;
    bool valid = v < n;
    int vv = valid ? v : n - 1;
    int cnt = g_cnt[vv];
    int nb = ((cnt + 3) & ~3) >> 2;
    const int4* ip = reinterpret_cast<const int4*>(g_idx + vv * CAP);
    float2 acc = make_float2(0.f, 0.f);
    for (int b = l; b < nb; b += 4) {
        int4 a = __ldg(ip + b);
        float2 v0 = __ldg(&g_t[a.x]);
        float2 v1 = __ldg(&g_t[a.y]);
        float2 v2 = __ldg(&g_t[a.z]);
        float2 v3 = __ldg(&g_t[a.w]);
        acc.x += v0.x + v1.x + v2.x + v3.x;
        acc.y += v0.y + v1.y + v2.y + v3.y;
    }
    acc.x += __shfl_xor_sync(0xffffffffu, acc.x, 1);
    acc.y += __shfl_xor_sync(0xffffffffu, acc.y, 1);
    acc.x += __shfl_xor_sync(0xffffffffu, acc.x, 2);
    acc.y += __shfl_xor_sync(0xffffffffu, acc.y, 2);
    if (valid && l == 0) {
        float2 self = g_t[v];
        float dv = g_dinv[v];
        float2 o;
        o.x = g_bf[0] + dv * (acc.x + self.x);
        o.y = g_bf[1] + dv * (acc.y + self.y);
        reinterpret_cast<float2*>(out)[v] = o;
        g_cnt[v] = 0;   // restore invariant for the next replay
    }
}

extern "C" void kernel_launch(void* const* d_in, const int* in_sizes, int n_in,
                              void* d_out, int out_size) {
    const float* x  = (const float*)d_in[0];
    const int*   ei = (const int*)d_in[1];
    const float* W1 = (const float*)d_in[2];
    const float* b1 = (const float*)d_in[3];
    const float* W2 = (const float*)d_in[4];
    const float* b2 = (const float*)d_in[5];
    const float* W3 = (const float*)d_in[6];
    const float* b3 = (const float*)d_in[7];
    const float* W4 = (const float*)d_in[8];
    const float* b4 = (const float*)d_in[9];
    const float* Wl = (const float*)d_in[10];
    const float* bl = (const float*)d_in[11];
    float* out = (float*)d_out;

    int n = in_sizes[0] / 8;   // 100000
    int E = in_sizes[1] / 2;   // 3200000
    const int* src = ei;       // edge_index[0]
    const int* dst = ei + E;   // edge_index[1]
    int E4 = E / 4;

    const int B = 256;
    auto blocks = [&](long total) { return (int)((total + B - 1) / B); };

    k_build<<<blocks(E4), B>>>(src, dst, E4, E);
    k_node<<<blocks(n), B>>>(x, W4, b4, Wl, bl, n);
    k_layer1<<<blocks((long)n * 32), B>>>(W1, b1, n);
    k_layer2<<<(n + 31) / 32, B>>>(W2, b2, n);
    k_layer3<<<(n + 31) / 32, B>>>(W3, b3, n);
    k_out<<<blocks((long)n * 4), B>>>(out, n);
}